// round 1
// baseline (speedup 1.0000x reference)
#include <cuda_runtime.h>
#include <cuda_bf16.h>
#include <cstdint>

// Problem constants
#define BB 2
#define LL 1024
#define DMODEL 1024
#define ED 2048
#define NSTATE 16
#define DTRANK 64
#define DCONV 4
#define BL (BB*LL)          // 2048 rows

// ---------------- scratch (no allocation allowed -> __device__ globals) -----
__device__ float g_xz[BB*LL*2*ED];      // (B,L,4096)  32 MB
__device__ float g_xconv[BB*LL*ED];     // (B,L,2048)  16 MB
__device__ float g_dbc[BL*96];          // (BL,96)
__device__ float g_delta[BB*LL*ED];     // (B,L,2048)  16 MB
__device__ float g_y[BB*LL*ED];         // (B,L,2048)  16 MB

// ---------------- generic fp32 SGEMM: C = A(MxK,lda) * B(KxN,ldb) ----------
// ACT: 0 = none, 1 = bias + softplus
template<int BM,int BN,int BK,int TM,int TN,int ACT>
__global__ void sgemm_kernel(const float* __restrict__ A,
                             const float* __restrict__ Bm,
                             float* __restrict__ C,
                             int M, int N, int K,
                             int lda, int ldb, int ldc,
                             const float* __restrict__ bias)
{
    constexpr int THREADS = (BM/TM)*(BN/TN);
    __shared__ float As[BK][BM];
    __shared__ float Bs[BK][BN];

    const int tid = threadIdx.x;
    const int tx  = tid % (BN/TN);
    const int ty  = tid / (BN/TN);
    const int rowBase = blockIdx.y * BM;
    const int colBase = blockIdx.x * BN;

    float acc[TM][TN];
    #pragma unroll
    for (int i = 0; i < TM; i++)
        #pragma unroll
        for (int j = 0; j < TN; j++) acc[i][j] = 0.f;

    constexpr int A_LOADS = (BM*BK/4) / THREADS;   // float4 loads per thread
    constexpr int B_LOADS = (BK*BN/4) / THREADS;
    static_assert(A_LOADS*THREADS == BM*BK/4, "A tile not divisible");
    static_assert(B_LOADS*THREADS == BK*BN/4, "B tile not divisible");

    for (int k0 = 0; k0 < K; k0 += BK) {
        #pragma unroll
        for (int i = 0; i < A_LOADS; i++) {
            int idx = tid + i*THREADS;
            int r  = idx / (BK/4);
            int c4 = idx % (BK/4);
            float4 v = *(const float4*)&A[(size_t)(rowBase + r)*lda + k0 + c4*4];
            As[c4*4+0][r] = v.x;
            As[c4*4+1][r] = v.y;
            As[c4*4+2][r] = v.z;
            As[c4*4+3][r] = v.w;
        }
        #pragma unroll
        for (int i = 0; i < B_LOADS; i++) {
            int idx = tid + i*THREADS;
            int r  = idx / (BN/4);
            int c4 = idx % (BN/4);
            *(float4*)&Bs[r][c4*4] =
                *(const float4*)&Bm[(size_t)(k0 + r)*ldb + colBase + c4*4];
        }
        __syncthreads();

        #pragma unroll
        for (int k = 0; k < BK; k++) {
            float ra[TM], rb[TN];
            #pragma unroll
            for (int i = 0; i < TM; i++) ra[i] = As[k][ty*TM + i];
            #pragma unroll
            for (int j = 0; j < TN; j++) rb[j] = Bs[k][tx*TN + j];
            #pragma unroll
            for (int i = 0; i < TM; i++)
                #pragma unroll
                for (int j = 0; j < TN; j++)
                    acc[i][j] += ra[i]*rb[j];
        }
        __syncthreads();
    }

    #pragma unroll
    for (int i = 0; i < TM; i++) {
        int r = rowBase + ty*TM + i;
        #pragma unroll
        for (int j = 0; j < TN; j++) {
            int c = colBase + tx*TN + j;
            float v = acc[i][j];
            if (ACT == 1) {
                v += bias[c];
                // softplus, numerically safe
                v = (v > 20.f) ? v : log1pf(expf(v));
            }
            C[(size_t)r*ldc + c] = v;
        }
    }
}

// ---------------- depthwise causal conv1d (K=4) + bias + SiLU --------------
// input: xc = g_xz[..., 0:ED] layout (B,L,2ED); output g_xconv (B,L,ED)
__global__ void conv_silu_kernel(const float* __restrict__ xz,
                                 const float* __restrict__ w,     // (ED,4)
                                 const float* __restrict__ bias,  // (ED,)
                                 float* __restrict__ out)
{
    int idx = blockIdx.x*blockDim.x + threadIdx.x;
    if (idx >= BB*LL*ED) return;
    int e = idx % ED;
    int l = (idx / ED) % LL;
    int b = idx / (ED*LL);

    const float4 wv = *(const float4*)&w[e*4];
    const float* base = xz + (size_t)b*LL*2*ED + e;

    float s = bias[e];
    if (l >= 3) s += wv.x * base[(size_t)(l-3)*2*ED];
    if (l >= 2) s += wv.y * base[(size_t)(l-2)*2*ED];
    if (l >= 1) s += wv.z * base[(size_t)(l-1)*2*ED];
    s += wv.w * base[(size_t)l*2*ED];

    // silu
    out[idx] = s / (1.f + __expf(-s));
}

// ---------------- fused selective scan + C-reduce + D skip + SiLU gate -----
// grid: (ED/16, B), block 256 (8 warps). Each warp: 2 e-channels, lanes&15 = n.
__global__ void scan_kernel(const float* __restrict__ delta,  // (B,L,ED)
                            const float* __restrict__ dbc,    // (BL,96)
                            const float* __restrict__ xconv,  // (B,L,ED)
                            const float* __restrict__ xz,     // (B,L,2ED), z at +ED
                            const float* __restrict__ A_log,  // (ED,16)
                            const float* __restrict__ Dw,     // (ED,)
                            float* __restrict__ y)            // (B,L,ED)
{
    const int b     = blockIdx.y;
    const int eBase = blockIdx.x * 16;
    const int tid   = threadIdx.x;
    const int warp  = tid >> 5;
    const int lane  = tid & 31;
    const int eLoc  = warp*2 + (lane >> 4);
    const int e     = eBase + eLoc;
    const int n     = lane & 15;

    const float Aval = -__expf(A_log[e*NSTATE + n]);
    const float Dval = Dw[e];

    const float* dRow  = delta + (size_t)b*LL*ED + e;
    const float* xRow  = xconv + (size_t)b*LL*ED + e;
    const float* zRow  = xz    + (size_t)b*LL*2*ED + ED + e;
    const float* bcRow = dbc   + (size_t)b*LL*96;

    __shared__ float ybuf[64][16];

    float h = 0.f;

    for (int l0 = 0; l0 < LL; l0 += 64) {
        #pragma unroll 4
        for (int li = 0; li < 64; li++) {
            const int l = l0 + li;
            const float dv = dRow[(size_t)l*ED];
            const float xv = xRow[(size_t)l*ED];
            const float Bn = bcRow[l*96 + DTRANK + n];
            const float Cn = bcRow[l*96 + DTRANK + NSTATE + n];

            const float dA = __expf(dv * Aval);
            h = dA*h + (dv*xv)*Bn;

            float c = h * Cn;
            c += __shfl_xor_sync(0xffffffffu, c, 8);
            c += __shfl_xor_sync(0xffffffffu, c, 4);
            c += __shfl_xor_sync(0xffffffffu, c, 2);
            c += __shfl_xor_sync(0xffffffffu, c, 1);

            if (n == 0) {
                const float zv  = zRow[(size_t)l*2*ED];
                const float sil = zv / (1.f + __expf(-zv));
                ybuf[li][eLoc] = (c + Dval*xv) * sil;
            }
        }
        __syncthreads();
        #pragma unroll
        for (int i = tid; i < 64*16; i += 256) {
            int li = i >> 4, ee = i & 15;
            y[((size_t)b*LL + l0 + li)*ED + eBase + ee] = ybuf[li][ee];
        }
        __syncthreads();
    }
}

// ---------------- launch ---------------------------------------------------
extern "C" void kernel_launch(void* const* d_in, const int* in_sizes, int n_in,
                              void* d_out, int out_size)
{
    const float* x          = (const float*)d_in[0];  // (B,L,1024)
    const float* in_proj_w  = (const float*)d_in[1];  // (1024,4096)
    const float* conv_w     = (const float*)d_in[2];  // (2048,1,4)
    const float* conv_b     = (const float*)d_in[3];  // (2048,)
    const float* x_proj_w   = (const float*)d_in[4];  // (2048,96)
    const float* dt_proj_w  = (const float*)d_in[5];  // (64,2048)
    const float* dt_proj_b  = (const float*)d_in[6];  // (2048,)
    const float* A_log      = (const float*)d_in[7];  // (2048,16)
    const float* Dw         = (const float*)d_in[8];  // (2048,)
    const float* out_proj_w = (const float*)d_in[9];  // (2048,1024)
    float* out = (float*)d_out;                       // (B,L,1024)

    float *xzP, *xconvP, *dbcP, *deltaP, *yP;
    cudaGetSymbolAddress((void**)&xzP,    g_xz);
    cudaGetSymbolAddress((void**)&xconvP, g_xconv);
    cudaGetSymbolAddress((void**)&dbcP,   g_dbc);
    cudaGetSymbolAddress((void**)&deltaP, g_delta);
    cudaGetSymbolAddress((void**)&yP,     g_y);

    // 1) xz = x @ in_proj_w : (2048 x 4096), K=1024
    {
        dim3 grid(2*ED/128, BL/128);
        sgemm_kernel<128,128,16,8,8,0><<<grid, 256>>>(
            x, in_proj_w, xzP, BL, 2*ED, DMODEL, DMODEL, 2*ED, 2*ED, nullptr);
    }

    // 2) depthwise causal conv + SiLU -> xconv
    {
        int total = BB*LL*ED;
        conv_silu_kernel<<<(total + 255)/256, 256>>>(xzP, conv_w, conv_b, xconvP);
    }

    // 3) dbc = xconv @ x_proj_w : (2048 x 96), K=2048
    {
        dim3 grid(1, BL/32);
        sgemm_kernel<32,96,32,2,6,0><<<grid, 256>>>(
            xconvP, x_proj_w, dbcP, BL, 96, ED, ED, 96, 96, nullptr);
    }

    // 4) delta = softplus(dbc[:, :64] @ dt_proj_w + b) : (2048 x 2048), K=64
    {
        dim3 grid(ED/64, BL/64);
        sgemm_kernel<64,64,16,4,4,1><<<grid, 256>>>(
            dbcP, dt_proj_w, deltaP, BL, ED, DTRANK, 96, ED, ED, dt_proj_b);
    }

    // 5) fused selective scan + gate -> y
    {
        dim3 grid(ED/16, BB);
        scan_kernel<<<grid, 256>>>(deltaP, dbcP, xconvP, xzP, A_log, Dw, yP);
    }

    // 6) out = y @ out_proj_w : (2048 x 1024), K=2048
    {
        dim3 grid(DMODEL/128, BL/128);
        sgemm_kernel<128,128,16,8,8,0><<<grid, 256>>>(
            yP, out_proj_w, out, BL, DMODEL, ED, ED, DMODEL, DMODEL, nullptr);
    }
}

// round 5
// speedup vs baseline: 1.3396x; 1.3396x over previous
#include <cuda_runtime.h>
#include <cuda_bf16.h>
#include <cstdint>

// ---------------- problem constants ----------------------------------------
#define BB 2
#define LL 1024
#define DMODEL 1024
#define ED 2048
#define NSTATE 16
#define DTRANK 64
#define BL (BB*LL)          // 2048 rows

// ---------------- scratch (no allocation allowed -> __device__ globals) ----
__device__ __align__(128) float g_xz[BB*LL*2*ED];      // (B,L,4096)
__device__ __align__(128) float g_xconv[BB*LL*ED];     // (B,L,2048)
__device__ __align__(128) float g_dbc[BL*96];          // (BL,96)
__device__ __align__(128) float g_delta[BB*LL*ED];     // (B,L,2048)
__device__ __align__(128) float g_y[BB*LL*ED];         // (B,L,2048)

// bf16 split-precision scratch
__device__ __align__(128) __nv_bfloat16 g_xh[BL*DMODEL];
__device__ __align__(128) __nv_bfloat16 g_xl[BL*DMODEL];
__device__ __align__(128) __nv_bfloat16 g_w1h[2*ED*DMODEL];
__device__ __align__(128) __nv_bfloat16 g_w1l[2*ED*DMODEL];
__device__ __align__(128) __nv_bfloat16 g_yh[BL*ED];
__device__ __align__(128) __nv_bfloat16 g_yl[BL*ED];
__device__ __align__(128) __nv_bfloat16 g_w6h[DMODEL*ED];
__device__ __align__(128) __nv_bfloat16 g_w6l[DMODEL*ED];

// ---------------- PTX helpers (sm_80-level only: no tcgen05/TMA!) ----------
__device__ __forceinline__ uint32_t smem_u32(const void* p) {
    uint32_t a;
    asm("{ .reg .u64 t; cvta.to.shared.u64 t, %1; cvt.u32.u64 %0, t; }"
        : "=r"(a) : "l"(p));
    return a;
}

#define CP_ASYNC16(dst, src) \
    asm volatile("cp.async.cg.shared.global [%0], [%1], 16;" \
                 :: "r"(dst), "l"(src) : "memory")
#define CP_COMMIT() asm volatile("cp.async.commit_group;" ::: "memory")
#define CP_WAIT(n)  asm volatile("cp.async.wait_group %0;" :: "n"(n) : "memory")

#define LDSM_X4(r0,r1,r2,r3, addr) \
    asm volatile("ldmatrix.sync.aligned.m8n8.x4.shared.b16 {%0,%1,%2,%3}, [%4];" \
                 : "=r"(r0),"=r"(r1),"=r"(r2),"=r"(r3) : "r"(addr))
#define LDSM_X2(r0,r1, addr) \
    asm volatile("ldmatrix.sync.aligned.m8n8.x2.shared.b16 {%0,%1}, [%2];" \
                 : "=r"(r0),"=r"(r1) : "r"(addr))

__device__ __forceinline__ void mma_bf16(float* c, const uint32_t* a, const uint32_t* b) {
    asm volatile(
        "mma.sync.aligned.m16n8k16.row.col.f32.bf16.bf16.f32 "
        "{%0,%1,%2,%3}, {%4,%5,%6,%7}, {%8,%9}, {%0,%1,%2,%3};"
        : "+f"(c[0]), "+f"(c[1]), "+f"(c[2]), "+f"(c[3])
        : "r"(a[0]), "r"(a[1]), "r"(a[2]), "r"(a[3]), "r"(b[0]), "r"(b[1]));
}

// ---------------- bf16x3 mma.sync GEMM: C(M,N) = A(M,K) * Bt(N,K)^T --------
// Tiles: CTA 128x128, BK=32, 8 warps of 64x32. Smem rows padded to 40 elems.
#define TPAD 40                          // bf16 elems per smem row (80 B)
#define TILE_B (128*TPAD*2)              // 10240 B per tile
#define STAGE_B (4*TILE_B)               // Ah,Al,Bh,Bl
#define GSM_BYTES (2*STAGE_B)            // 81920 B

__global__ __launch_bounds__(256, 1)
void gemm_bf16x3(const __nv_bfloat16* __restrict__ Ah, const __nv_bfloat16* __restrict__ Al,
                 const __nv_bfloat16* __restrict__ Bh, const __nv_bfloat16* __restrict__ Bl,
                 float* __restrict__ C, int M, int N, int K)
{
    extern __shared__ __align__(128) char smem[];
    const uint32_t sb = smem_u32(smem);
    const int tid  = threadIdx.x;
    const int lane = tid & 31;
    const int warp = tid >> 5;
    const int wm   = warp >> 2;          // 0..1  (M)
    const int wn   = warp & 3;           // 0..3  (N)
    const int m0 = blockIdx.y * 128, n0 = blockIdx.x * 128;
    const int NK = K >> 5;               // K/32 chunks

    const __nv_bfloat16* gbase[4] = {
        Ah + (size_t)m0 * K, Al + (size_t)m0 * K,
        Bh + (size_t)n0 * K, Bl + (size_t)n0 * K };

    // per-thread load geometry: 2048 16B chunks/stage, 8 per thread
    auto loadStage = [&](int kc) {
        const uint32_t stg = sb + (kc & 1) * STAGE_B;
        const int koff = kc * 32;
        #pragma unroll
        for (int i = 0; i < 8; i++) {
            const int c  = tid + i * 256;
            const int t  = c >> 9;
            const int cc = c & 511;
            const int row = cc >> 2, q = cc & 3;
            const __nv_bfloat16* src = gbase[t] + (size_t)row * K + koff + q * 8;
            const uint32_t dst = stg + t * TILE_B + (row * TPAD + q * 8) * 2;
            CP_ASYNC16(dst, src);
        }
    };

    float acc[4][4][4];
    #pragma unroll
    for (int i = 0; i < 4; i++)
        #pragma unroll
        for (int j = 0; j < 4; j++)
            #pragma unroll
            for (int k = 0; k < 4; k++) acc[i][j][k] = 0.f;

    const uint32_t aRow = (uint32_t)(wm * 64 + (lane & 15)) * (TPAD * 2);
    const uint32_t aK8  = (uint32_t)(lane >> 4) * 16;
    const uint32_t bRow = (uint32_t)(wn * 32 + (lane & 7)) * (TPAD * 2);
    const uint32_t bK8  = (uint32_t)((lane >> 3) & 1) * 16;

    loadStage(0);
    CP_COMMIT();

    for (int kc = 0; kc < NK; kc++) {
        if (kc + 1 < NK) { loadStage(kc + 1); CP_COMMIT(); CP_WAIT(1); }
        else             { CP_WAIT(0); }
        __syncthreads();

        const uint32_t stg = sb + (kc & 1) * STAGE_B;
        const uint32_t sAh = stg,            sAl = stg + TILE_B;
        const uint32_t sBh = stg + 2*TILE_B, sBl = stg + 3*TILE_B;

        #pragma unroll
        for (int ks = 0; ks < 2; ks++) {
            const uint32_t kOffA = ks * 32 + aK8;
            const uint32_t kOffB = ks * 32 + bK8;

            uint32_t ah[4][4], al[4][4], bh[4][2], bl[4][2];
            #pragma unroll
            for (int mf = 0; mf < 4; mf++) {
                const uint32_t ro = aRow + (uint32_t)mf * 16 * (TPAD * 2);
                LDSM_X4(ah[mf][0], ah[mf][1], ah[mf][2], ah[mf][3], sAh + ro + kOffA);
                LDSM_X4(al[mf][0], al[mf][1], al[mf][2], al[mf][3], sAl + ro + kOffA);
            }
            #pragma unroll
            for (int nf = 0; nf < 4; nf++) {
                const uint32_t ro = bRow + (uint32_t)nf * 8 * (TPAD * 2);
                LDSM_X2(bh[nf][0], bh[nf][1], sBh + ro + kOffB);
                LDSM_X2(bl[nf][0], bl[nf][1], sBl + ro + kOffB);
            }
            #pragma unroll
            for (int mf = 0; mf < 4; mf++)
                #pragma unroll
                for (int nf = 0; nf < 4; nf++) {
                    mma_bf16(acc[mf][nf], ah[mf], bh[nf]);
                    mma_bf16(acc[mf][nf], ah[mf], bl[nf]);
                    mma_bf16(acc[mf][nf], al[mf], bh[nf]);
                }
        }
        __syncthreads();
    }

    // epilogue: direct fp32 stores (v2)
    const int mBase = m0 + wm * 64 + (lane >> 2);
    const int nBase = n0 + wn * 32 + (lane & 3) * 2;
    #pragma unroll
    for (int mf = 0; mf < 4; mf++)
        #pragma unroll
        for (int nf = 0; nf < 4; nf++) {
            const int r = mBase + mf * 16;
            const int c = nBase + nf * 8;
            *(float2*)&C[(size_t)r * N + c]       = make_float2(acc[mf][nf][0], acc[mf][nf][1]);
            *(float2*)&C[(size_t)(r + 8) * N + c] = make_float2(acc[mf][nf][2], acc[mf][nf][3]);
        }
}

// ---------------- weight transpose + bf16 hi/lo split ----------------------
__global__ void wconv_kernel(const float* __restrict__ W,
                             __nv_bfloat16* __restrict__ Th,
                             __nv_bfloat16* __restrict__ Tl, int K, int N)
{
    __shared__ float t[32][33];
    const int bx = blockIdx.x * 32;  // n
    const int by = blockIdx.y * 32;  // k
    const int tx = threadIdx.x, ty = threadIdx.y;
    #pragma unroll
    for (int j = 0; j < 32; j += 8)
        t[ty + j][tx] = W[(size_t)(by + ty + j) * N + bx + tx];
    __syncthreads();
    #pragma unroll
    for (int j = 0; j < 32; j += 8) {
        const float v = t[tx][ty + j];
        const __nv_bfloat16 h = __float2bfloat16(v);
        const float r = v - __bfloat162float(h);
        const size_t o = (size_t)(bx + ty + j) * K + by + tx;
        Th[o] = h;  Tl[o] = __float2bfloat16(r);
    }
}

// ---------------- activation bf16 hi/lo split ------------------------------
__global__ void aconv_kernel(const float* __restrict__ A,
                             __nv_bfloat16* __restrict__ H,
                             __nv_bfloat16* __restrict__ L, int n)
{
    const int i = blockIdx.x * blockDim.x + threadIdx.x;
    if (i >= n) return;
    const float v = A[i];
    const __nv_bfloat16 h = __float2bfloat16(v);
    H[i] = h;
    L[i] = __float2bfloat16(v - __bfloat162float(h));
}

// ---------------- fp32 SIMT SGEMM (small GEMMs) ----------------------------
template<int BM,int BN,int BK,int TM,int TN,int ACT>
__global__ void sgemm_kernel(const float* __restrict__ A,
                             const float* __restrict__ Bm,
                             float* __restrict__ C,
                             int M, int N, int K,
                             int lda, int ldb, int ldc,
                             const float* __restrict__ bias)
{
    constexpr int THREADS = (BM/TM)*(BN/TN);
    __shared__ float As[BK][BM];
    __shared__ float Bs[BK][BN];

    const int tid = threadIdx.x;
    const int tx  = tid % (BN/TN);
    const int ty  = tid / (BN/TN);
    const int rowBase = blockIdx.y * BM;
    const int colBase = blockIdx.x * BN;

    float acc[TM][TN];
    #pragma unroll
    for (int i = 0; i < TM; i++)
        #pragma unroll
        for (int j = 0; j < TN; j++) acc[i][j] = 0.f;

    constexpr int A_LOADS = (BM*BK/4) / THREADS;
    constexpr int B_LOADS = (BK*BN/4) / THREADS;
    static_assert(A_LOADS*THREADS == BM*BK/4, "A tile not divisible");
    static_assert(B_LOADS*THREADS == BK*BN/4, "B tile not divisible");

    for (int k0 = 0; k0 < K; k0 += BK) {
        #pragma unroll
        for (int i = 0; i < A_LOADS; i++) {
            int idx = tid + i*THREADS;
            int r  = idx / (BK/4);
            int c4 = idx % (BK/4);
            float4 v = *(const float4*)&A[(size_t)(rowBase + r)*lda + k0 + c4*4];
            As[c4*4+0][r] = v.x;
            As[c4*4+1][r] = v.y;
            As[c4*4+2][r] = v.z;
            As[c4*4+3][r] = v.w;
        }
        #pragma unroll
        for (int i = 0; i < B_LOADS; i++) {
            int idx = tid + i*THREADS;
            int r  = idx / (BN/4);
            int c4 = idx % (BN/4);
            *(float4*)&Bs[r][c4*4] =
                *(const float4*)&Bm[(size_t)(k0 + r)*ldb + colBase + c4*4];
        }
        __syncthreads();

        #pragma unroll
        for (int k = 0; k < BK; k++) {
            float ra[TM], rb[TN];
            #pragma unroll
            for (int i = 0; i < TM; i++) ra[i] = As[k][ty*TM + i];
            #pragma unroll
            for (int j = 0; j < TN; j++) rb[j] = Bs[k][tx*TN + j];
            #pragma unroll
            for (int i = 0; i < TM; i++)
                #pragma unroll
                for (int j = 0; j < TN; j++)
                    acc[i][j] += ra[i]*rb[j];
        }
        __syncthreads();
    }

    #pragma unroll
    for (int i = 0; i < TM; i++) {
        int r = rowBase + ty*TM + i;
        #pragma unroll
        for (int j = 0; j < TN; j++) {
            int c = colBase + tx*TN + j;
            float v = acc[i][j];
            if (ACT == 1) {
                v += bias[c];
                v = (v > 20.f) ? v : log1pf(expf(v));
            }
            C[(size_t)r*ldc + c] = v;
        }
    }
}

// ---------------- depthwise causal conv1d (K=4) + bias + SiLU --------------
__global__ void conv_silu_kernel(const float* __restrict__ xz,
                                 const float* __restrict__ w,
                                 const float* __restrict__ bias,
                                 float* __restrict__ out)
{
    int idx = blockIdx.x*blockDim.x + threadIdx.x;
    if (idx >= BB*LL*ED) return;
    int e = idx % ED;
    int l = (idx / ED) % LL;
    int b = idx / (ED*LL);

    const float4 wv = *(const float4*)&w[e*4];
    const float* base = xz + (size_t)b*LL*2*ED + e;

    float s = bias[e];
    if (l >= 3) s += wv.x * base[(size_t)(l-3)*2*ED];
    if (l >= 2) s += wv.y * base[(size_t)(l-2)*2*ED];
    if (l >= 1) s += wv.z * base[(size_t)(l-1)*2*ED];
    s += wv.w * base[(size_t)l*2*ED];

    out[idx] = s / (1.f + __expf(-s));
}

// ---------------- fused selective scan + C-reduce + D skip + SiLU gate -----
__global__ void scan_kernel(const float* __restrict__ delta,
                            const float* __restrict__ dbc,
                            const float* __restrict__ xconv,
                            const float* __restrict__ xz,
                            const float* __restrict__ A_log,
                            const float* __restrict__ Dw,
                            float* __restrict__ y)
{
    const int b     = blockIdx.y;
    const int eBase = blockIdx.x * 16;
    const int tid   = threadIdx.x;
    const int warp  = tid >> 5;
    const int lane  = tid & 31;
    const int eLoc  = warp*2 + (lane >> 4);
    const int e     = eBase + eLoc;
    const int n     = lane & 15;

    const float Aval = -__expf(A_log[e*NSTATE + n]);
    const float Dval = Dw[e];

    const float* dRow  = delta + (size_t)b*LL*ED + e;
    const float* xRow  = xconv + (size_t)b*LL*ED + e;
    const float* zRow  = xz    + (size_t)b*LL*2*ED + ED + e;
    const float* bcRow = dbc   + (size_t)b*LL*96;

    __shared__ float ybuf[64][16];

    float h = 0.f;

    for (int l0 = 0; l0 < LL; l0 += 64) {
        #pragma unroll 4
        for (int li = 0; li < 64; li++) {
            const int l = l0 + li;
            const float dv = dRow[(size_t)l*ED];
            const float xv = xRow[(size_t)l*ED];
            const float Bn = bcRow[l*96 + DTRANK + n];
            const float Cn = bcRow[l*96 + DTRANK + NSTATE + n];

            const float dA = __expf(dv * Aval);
            h = dA*h + (dv*xv)*Bn;

            float c = h * Cn;
            c += __shfl_xor_sync(0xffffffffu, c, 8);
            c += __shfl_xor_sync(0xffffffffu, c, 4);
            c += __shfl_xor_sync(0xffffffffu, c, 2);
            c += __shfl_xor_sync(0xffffffffu, c, 1);

            if (n == 0) {
                const float zv  = zRow[(size_t)l*2*ED];
                const float sil = zv / (1.f + __expf(-zv));
                ybuf[li][eLoc] = (c + Dval*xv) * sil;
            }
        }
        __syncthreads();
        #pragma unroll
        for (int i = tid; i < 64*16; i += 256) {
            int li = i >> 4, ee = i & 15;
            y[((size_t)b*LL + l0 + li)*ED + eBase + ee] = ybuf[li][ee];
        }
        __syncthreads();
    }
}

// ---------------- launch ---------------------------------------------------
extern "C" void kernel_launch(void* const* d_in, const int* in_sizes, int n_in,
                              void* d_out, int out_size)
{
    const float* x          = (const float*)d_in[0];  // (B,L,1024)
    const float* in_proj_w  = (const float*)d_in[1];  // (1024,4096)
    const float* conv_w     = (const float*)d_in[2];  // (2048,1,4)
    const float* conv_b     = (const float*)d_in[3];  // (2048,)
    const float* x_proj_w   = (const float*)d_in[4];  // (2048,96)
    const float* dt_proj_w  = (const float*)d_in[5];  // (64,2048)
    const float* dt_proj_b  = (const float*)d_in[6];  // (2048,)
    const float* A_log      = (const float*)d_in[7];  // (2048,16)
    const float* Dw         = (const float*)d_in[8];  // (2048,)
    const float* out_proj_w = (const float*)d_in[9];  // (2048,1024)
    float* out = (float*)d_out;                       // (B,L,1024)

    float *xzP, *xconvP, *dbcP, *deltaP, *yP;
    cudaGetSymbolAddress((void**)&xzP,    g_xz);
    cudaGetSymbolAddress((void**)&xconvP, g_xconv);
    cudaGetSymbolAddress((void**)&dbcP,   g_dbc);
    cudaGetSymbolAddress((void**)&deltaP, g_delta);
    cudaGetSymbolAddress((void**)&yP,     g_y);

    __nv_bfloat16 *xhP, *xlP, *w1hP, *w1lP, *yhP, *ylP, *w6hP, *w6lP;
    cudaGetSymbolAddress((void**)&xhP,  g_xh);
    cudaGetSymbolAddress((void**)&xlP,  g_xl);
    cudaGetSymbolAddress((void**)&w1hP, g_w1h);
    cudaGetSymbolAddress((void**)&w1lP, g_w1l);
    cudaGetSymbolAddress((void**)&yhP,  g_yh);
    cudaGetSymbolAddress((void**)&ylP,  g_yl);
    cudaGetSymbolAddress((void**)&w6hP, g_w6h);
    cudaGetSymbolAddress((void**)&w6lP, g_w6l);

    cudaFuncSetAttribute(gemm_bf16x3,
                         cudaFuncAttributeMaxDynamicSharedMemorySize, GSM_BYTES);

    // 0) weight transpose + split
    wconv_kernel<<<dim3(2*ED/32, DMODEL/32), dim3(32,8)>>>(in_proj_w,  w1hP, w1lP, DMODEL, 2*ED);
    wconv_kernel<<<dim3(DMODEL/32, ED/32),   dim3(32,8)>>>(out_proj_w, w6hP, w6lP, ED, DMODEL);

    // 0b) x split
    aconv_kernel<<<(BL*DMODEL + 255)/256, 256>>>(x, xhP, xlP, BL*DMODEL);

    // 1) xz = x @ W1 : (2048 x 4096), K=1024 — bf16x3 mma.sync
    gemm_bf16x3<<<dim3(2*ED/128, BL/128), 256, GSM_BYTES>>>(
        xhP, xlP, w1hP, w1lP, xzP, BL, 2*ED, DMODEL);

    // 2) depthwise causal conv + SiLU -> xconv
    conv_silu_kernel<<<(BB*LL*ED + 255)/256, 256>>>(xzP, conv_w, conv_b, xconvP);

    // 3) dbc = xconv @ x_proj_w : (2048 x 96), K=2048
    {
        dim3 grid(2, BL/32);
        sgemm_kernel<32,48,32,2,6,0><<<grid, 128>>>(
            xconvP, x_proj_w, dbcP, BL, 96, ED, ED, 96, 96, nullptr);
    }

    // 4) delta = softplus(dbc[:, :64] @ dt_proj_w + b) : (2048 x 2048), K=64
    {
        dim3 grid(ED/64, BL/64);
        sgemm_kernel<64,64,16,4,4,1><<<grid, 256>>>(
            dbcP, dt_proj_w, deltaP, BL, ED, DTRANK, 96, ED, ED, dt_proj_b);
    }

    // 5) fused selective scan + gate -> y
    {
        dim3 grid(ED/16, BB);
        scan_kernel<<<grid, 256>>>(deltaP, dbcP, xconvP, xzP, A_log, Dw, yP);
    }

    // 5b) y split
    aconv_kernel<<<(BL*ED + 255)/256, 256>>>(yP, yhP, ylP, BL*ED);

    // 6) out = y @ W6 : (2048 x 1024), K=2048 — bf16x3 mma.sync
    gemm_bf16x3<<<dim3(DMODEL/128, BL/128), 256, GSM_BYTES>>>(
        yhP, ylP, w6hP, w6lP, out, BL, DMODEL, ED);
}

// round 6
// speedup vs baseline: 2.1335x; 1.5927x over previous
#include <cuda_runtime.h>
#include <cuda_bf16.h>
#include <cstdint>

// ---------------- problem constants ----------------------------------------
#define BB 2
#define LL 1024
#define DMODEL 1024
#define ED 2048
#define NSTATE 16
#define DTRANK 64
#define BL (BB*LL)          // 2048 rows

// ---------------- scratch (no allocation allowed -> __device__ globals) ----
__device__ __align__(128) float g_xz[BB*LL*2*ED];      // (B,L,4096)
__device__ __align__(128) float g_xconv[BB*LL*ED];     // (B,L,2048)
__device__ __align__(128) float g_dbc[BL*96];          // (BL,96)
__device__ __align__(128) float g_delta[BB*LL*ED];     // (B,L,2048)

// bf16 split-precision scratch
__device__ __align__(128) __nv_bfloat16 g_xh[BL*DMODEL];
__device__ __align__(128) __nv_bfloat16 g_xl[BL*DMODEL];
__device__ __align__(128) __nv_bfloat16 g_w1h[2*ED*DMODEL];
__device__ __align__(128) __nv_bfloat16 g_w1l[2*ED*DMODEL];
__device__ __align__(128) __nv_bfloat16 g_yh[BL*ED];
__device__ __align__(128) __nv_bfloat16 g_yl[BL*ED];
__device__ __align__(128) __nv_bfloat16 g_w6h[DMODEL*ED];
__device__ __align__(128) __nv_bfloat16 g_w6l[DMODEL*ED];

// ---------------- PTX helpers (sm_80-level only: no tcgen05/TMA!) ----------
__device__ __forceinline__ uint32_t smem_u32(const void* p) {
    uint32_t a;
    asm("{ .reg .u64 t; cvta.to.shared.u64 t, %1; cvt.u32.u64 %0, t; }"
        : "=r"(a) : "l"(p));
    return a;
}

#define CP_ASYNC16(dst, src) \
    asm volatile("cp.async.cg.shared.global [%0], [%1], 16;" \
                 :: "r"(dst), "l"(src) : "memory")
#define CP_COMMIT() asm volatile("cp.async.commit_group;" ::: "memory")
#define CP_WAIT(n)  asm volatile("cp.async.wait_group %0;" :: "n"(n) : "memory")

#define LDSM_X4(r0,r1,r2,r3, addr) \
    asm volatile("ldmatrix.sync.aligned.m8n8.x4.shared.b16 {%0,%1,%2,%3}, [%4];" \
                 : "=r"(r0),"=r"(r1),"=r"(r2),"=r"(r3) : "r"(addr))
#define LDSM_X2(r0,r1, addr) \
    asm volatile("ldmatrix.sync.aligned.m8n8.x2.shared.b16 {%0,%1}, [%2];" \
                 : "=r"(r0),"=r"(r1) : "r"(addr))

__device__ __forceinline__ void mma_bf16(float* c, const uint32_t* a, const uint32_t* b) {
    asm volatile(
        "mma.sync.aligned.m16n8k16.row.col.f32.bf16.bf16.f32 "
        "{%0,%1,%2,%3}, {%4,%5,%6,%7}, {%8,%9}, {%0,%1,%2,%3};"
        : "+f"(c[0]), "+f"(c[1]), "+f"(c[2]), "+f"(c[3])
        : "r"(a[0]), "r"(a[1]), "r"(a[2]), "r"(a[3]), "r"(b[0]), "r"(b[1]));
}

// ---------------- bf16x3 mma.sync GEMM: C(M,N) = A(M,K) * Bt(N,K)^T --------
#define TPAD 40                          // bf16 elems per smem row (80 B)
#define TILE_B (128*TPAD*2)              // 10240 B per tile
#define STAGE_B (4*TILE_B)               // Ah,Al,Bh,Bl
#define GSM_BYTES (2*STAGE_B)            // 81920 B

__global__ __launch_bounds__(256, 1)
void gemm_bf16x3(const __nv_bfloat16* __restrict__ Ah, const __nv_bfloat16* __restrict__ Al,
                 const __nv_bfloat16* __restrict__ Bh, const __nv_bfloat16* __restrict__ Bl,
                 float* __restrict__ C, int M, int N, int K)
{
    extern __shared__ __align__(128) char smem[];
    const uint32_t sb = smem_u32(smem);
    const int tid  = threadIdx.x;
    const int lane = tid & 31;
    const int warp = tid >> 5;
    const int wm   = warp >> 2;          // 0..1  (M)
    const int wn   = warp & 3;           // 0..3  (N)
    const int m0 = blockIdx.y * 128, n0 = blockIdx.x * 128;
    const int NK = K >> 5;               // K/32 chunks

    const __nv_bfloat16* gbase[4] = {
        Ah + (size_t)m0 * K, Al + (size_t)m0 * K,
        Bh + (size_t)n0 * K, Bl + (size_t)n0 * K };

    auto loadStage = [&](int kc) {
        const uint32_t stg = sb + (kc & 1) * STAGE_B;
        const int koff = kc * 32;
        #pragma unroll
        for (int i = 0; i < 8; i++) {
            const int c  = tid + i * 256;
            const int t  = c >> 9;
            const int cc = c & 511;
            const int row = cc >> 2, q = cc & 3;
            const __nv_bfloat16* src = gbase[t] + (size_t)row * K + koff + q * 8;
            const uint32_t dst = stg + t * TILE_B + (row * TPAD + q * 8) * 2;
            CP_ASYNC16(dst, src);
        }
    };

    float acc[4][4][4];
    #pragma unroll
    for (int i = 0; i < 4; i++)
        #pragma unroll
        for (int j = 0; j < 4; j++)
            #pragma unroll
            for (int k = 0; k < 4; k++) acc[i][j][k] = 0.f;

    const uint32_t aRow = (uint32_t)(wm * 64 + (lane & 15)) * (TPAD * 2);
    const uint32_t aK8  = (uint32_t)(lane >> 4) * 16;
    const uint32_t bRow = (uint32_t)(wn * 32 + (lane & 7)) * (TPAD * 2);
    const uint32_t bK8  = (uint32_t)((lane >> 3) & 1) * 16;

    loadStage(0);
    CP_COMMIT();

    for (int kc = 0; kc < NK; kc++) {
        if (kc + 1 < NK) { loadStage(kc + 1); CP_COMMIT(); CP_WAIT(1); }
        else             { CP_WAIT(0); }
        __syncthreads();

        const uint32_t stg = sb + (kc & 1) * STAGE_B;
        const uint32_t sAh = stg,            sAl = stg + TILE_B;
        const uint32_t sBh = stg + 2*TILE_B, sBl = stg + 3*TILE_B;

        #pragma unroll
        for (int ks = 0; ks < 2; ks++) {
            const uint32_t kOffA = ks * 32 + aK8;
            const uint32_t kOffB = ks * 32 + bK8;

            uint32_t ah[4][4], al[4][4], bh[4][2], bl[4][2];
            #pragma unroll
            for (int mf = 0; mf < 4; mf++) {
                const uint32_t ro = aRow + (uint32_t)mf * 16 * (TPAD * 2);
                LDSM_X4(ah[mf][0], ah[mf][1], ah[mf][2], ah[mf][3], sAh + ro + kOffA);
                LDSM_X4(al[mf][0], al[mf][1], al[mf][2], al[mf][3], sAl + ro + kOffA);
            }
            #pragma unroll
            for (int nf = 0; nf < 4; nf++) {
                const uint32_t ro = bRow + (uint32_t)nf * 8 * (TPAD * 2);
                LDSM_X2(bh[nf][0], bh[nf][1], sBh + ro + kOffB);
                LDSM_X2(bl[nf][0], bl[nf][1], sBl + ro + kOffB);
            }
            #pragma unroll
            for (int mf = 0; mf < 4; mf++)
                #pragma unroll
                for (int nf = 0; nf < 4; nf++) {
                    mma_bf16(acc[mf][nf], ah[mf], bh[nf]);
                    mma_bf16(acc[mf][nf], ah[mf], bl[nf]);
                    mma_bf16(acc[mf][nf], al[mf], bh[nf]);
                }
        }
        __syncthreads();
    }

    const int mBase = m0 + wm * 64 + (lane >> 2);
    const int nBase = n0 + wn * 32 + (lane & 3) * 2;
    #pragma unroll
    for (int mf = 0; mf < 4; mf++)
        #pragma unroll
        for (int nf = 0; nf < 4; nf++) {
            const int r = mBase + mf * 16;
            const int c = nBase + nf * 8;
            *(float2*)&C[(size_t)r * N + c]       = make_float2(acc[mf][nf][0], acc[mf][nf][1]);
            *(float2*)&C[(size_t)(r + 8) * N + c] = make_float2(acc[mf][nf][2], acc[mf][nf][3]);
        }
}

// ---------------- weight transpose + bf16 hi/lo split ----------------------
__global__ void wconv_kernel(const float* __restrict__ W,
                             __nv_bfloat16* __restrict__ Th,
                             __nv_bfloat16* __restrict__ Tl, int K, int N)
{
    __shared__ float t[32][33];
    const int bx = blockIdx.x * 32;  // n
    const int by = blockIdx.y * 32;  // k
    const int tx = threadIdx.x, ty = threadIdx.y;
    #pragma unroll
    for (int j = 0; j < 32; j += 8)
        t[ty + j][tx] = W[(size_t)(by + ty + j) * N + bx + tx];
    __syncthreads();
    #pragma unroll
    for (int j = 0; j < 32; j += 8) {
        const float v = t[tx][ty + j];
        const __nv_bfloat16 h = __float2bfloat16(v);
        const float r = v - __bfloat162float(h);
        const size_t o = (size_t)(bx + ty + j) * K + by + tx;
        Th[o] = h;  Tl[o] = __float2bfloat16(r);
    }
}

// ---------------- activation bf16 hi/lo split ------------------------------
__global__ void aconv_kernel(const float* __restrict__ A,
                             __nv_bfloat16* __restrict__ H,
                             __nv_bfloat16* __restrict__ L, int n)
{
    const int i = blockIdx.x * blockDim.x + threadIdx.x;
    if (i >= n) return;
    const float v = A[i];
    const __nv_bfloat16 h = __float2bfloat16(v);
    H[i] = h;
    L[i] = __float2bfloat16(v - __bfloat162float(h));
}

// ---------------- fp32 SIMT SGEMM (small GEMMs) ----------------------------
template<int BM,int BN,int BK,int TM,int TN,int ACT>
__global__ void sgemm_kernel(const float* __restrict__ A,
                             const float* __restrict__ Bm,
                             float* __restrict__ C,
                             int M, int N, int K,
                             int lda, int ldb, int ldc,
                             const float* __restrict__ bias)
{
    constexpr int THREADS = (BM/TM)*(BN/TN);
    __shared__ float As[BK][BM];
    __shared__ float Bs[BK][BN];

    const int tid = threadIdx.x;
    const int tx  = tid % (BN/TN);
    const int ty  = tid / (BN/TN);
    const int rowBase = blockIdx.y * BM;
    const int colBase = blockIdx.x * BN;

    float acc[TM][TN];
    #pragma unroll
    for (int i = 0; i < TM; i++)
        #pragma unroll
        for (int j = 0; j < TN; j++) acc[i][j] = 0.f;

    constexpr int A_LOADS = (BM*BK/4) / THREADS;
    constexpr int B_LOADS = (BK*BN/4) / THREADS;
    static_assert(A_LOADS*THREADS == BM*BK/4, "A tile not divisible");
    static_assert(B_LOADS*THREADS == BK*BN/4, "B tile not divisible");

    for (int k0 = 0; k0 < K; k0 += BK) {
        #pragma unroll
        for (int i = 0; i < A_LOADS; i++) {
            int idx = tid + i*THREADS;
            int r  = idx / (BK/4);
            int c4 = idx % (BK/4);
            float4 v = *(const float4*)&A[(size_t)(rowBase + r)*lda + k0 + c4*4];
            As[c4*4+0][r] = v.x;
            As[c4*4+1][r] = v.y;
            As[c4*4+2][r] = v.z;
            As[c4*4+3][r] = v.w;
        }
        #pragma unroll
        for (int i = 0; i < B_LOADS; i++) {
            int idx = tid + i*THREADS;
            int r  = idx / (BN/4);
            int c4 = idx % (BN/4);
            *(float4*)&Bs[r][c4*4] =
                *(const float4*)&Bm[(size_t)(k0 + r)*ldb + colBase + c4*4];
        }
        __syncthreads();

        #pragma unroll
        for (int k = 0; k < BK; k++) {
            float ra[TM], rb[TN];
            #pragma unroll
            for (int i = 0; i < TM; i++) ra[i] = As[k][ty*TM + i];
            #pragma unroll
            for (int j = 0; j < TN; j++) rb[j] = Bs[k][tx*TN + j];
            #pragma unroll
            for (int i = 0; i < TM; i++)
                #pragma unroll
                for (int j = 0; j < TN; j++)
                    acc[i][j] += ra[i]*rb[j];
        }
        __syncthreads();
    }

    #pragma unroll
    for (int i = 0; i < TM; i++) {
        int r = rowBase + ty*TM + i;
        #pragma unroll
        for (int j = 0; j < TN; j++) {
            int c = colBase + tx*TN + j;
            float v = acc[i][j];
            if (ACT == 1) {
                v += bias[c];
                v = (v > 20.f) ? v : log1pf(expf(v));
            }
            C[(size_t)r*ldc + c] = v;
        }
    }
}

// ---------------- depthwise causal conv1d (K=4) + bias + SiLU --------------
__global__ void conv_silu_kernel(const float* __restrict__ xz,
                                 const float* __restrict__ w,
                                 const float* __restrict__ bias,
                                 float* __restrict__ out)
{
    int idx = blockIdx.x*blockDim.x + threadIdx.x;
    if (idx >= BB*LL*ED) return;
    int e = idx % ED;
    int l = (idx / ED) % LL;
    int b = idx / (ED*LL);

    const float4 wv = *(const float4*)&w[e*4];
    const float* base = xz + (size_t)b*LL*2*ED + e;

    float s = bias[e];
    if (l >= 3) s += wv.x * base[(size_t)(l-3)*2*ED];
    if (l >= 2) s += wv.y * base[(size_t)(l-2)*2*ED];
    if (l >= 1) s += wv.z * base[(size_t)(l-1)*2*ED];
    s += wv.w * base[(size_t)l*2*ED];

    out[idx] = s / (1.f + __expf(-s));
}

// ---------------- fused selective scan v2: thread-per-e, 16 states in regs -
// deltaA_n = exp(delta*A_n); when A_n == -(n+1) (checked per-thread) use
// t = exp(-delta), deltaA_n = t^(n+1): 1 exp instead of 16.
// Emits yh/yl bf16 split directly (feeds gemm6), no fp32 y round-trip.
__global__ __launch_bounds__(32)
void scan2_kernel(const float* __restrict__ delta,  // (B,L,ED)
                  const float* __restrict__ dbc,    // (BL,96)
                  const float* __restrict__ xconv,  // (B,L,ED)
                  const float* __restrict__ xz,     // (B,L,2ED), z at +ED
                  const float* __restrict__ A_log,  // (ED,16)
                  const float* __restrict__ Dw,     // (ED,)
                  __nv_bfloat16* __restrict__ yh,
                  __nv_bfloat16* __restrict__ yl)
{
    const int b   = blockIdx.y;
    const int tid = threadIdx.x;
    const int e   = blockIdx.x * 32 + tid;

    __shared__ __align__(16) float sBC[128][36];   // [li][0..15]=B, [16..31]=C

    float an[16];
    bool ok = true;
    #pragma unroll
    for (int n = 0; n < 16; n++) {
        an[n] = -__expf(A_log[e*NSTATE + n]);
        ok = ok && (fabsf(an[n] + (float)(n+1)) < 1e-4f * (float)(n+1));
    }
    const float Dval = Dw[e];

    const float* dRow   = delta + (size_t)b*LL*ED + e;
    const float* xRow   = xconv + (size_t)b*LL*ED + e;
    const float* zRow   = xz    + (size_t)b*LL*2*ED + ED + e;
    const float* bcBase = dbc   + (size_t)b*LL*96;
    __nv_bfloat16* yhRow = yh + (size_t)b*LL*ED + e;
    __nv_bfloat16* ylRow = yl + (size_t)b*LL*ED + e;

    float h[16];
    #pragma unroll
    for (int n = 0; n < 16; n++) h[n] = 0.f;

    float pd[2][4], px[2][4], pz[2][4];
    #pragma unroll
    for (int j = 0; j < 4; j++) {
        pd[0][j] = dRow[(size_t)j*ED];
        px[0][j] = xRow[(size_t)j*ED];
        pz[0][j] = zRow[(size_t)j*2*ED];
    }

    for (int g = 0; g < LL/4; g++) {
        const int l0 = g * 4;
        if ((l0 & 127) == 0) {
            __syncwarp();
            for (int i = tid; i < 128*8; i += 32) {
                const int li = i >> 3, q = i & 7;
                const float4 v = *(const float4*)&bcBase[(size_t)(l0+li)*96 + DTRANK + q*4];
                *(float4*)&sBC[li][q*4] = v;
            }
            __syncwarp();
        }
        const int cur = g & 1, nxt = cur ^ 1;
        if (g + 1 < LL/4) {
            const int l1 = l0 + 4;
            #pragma unroll
            for (int j = 0; j < 4; j++) {
                pd[nxt][j] = dRow[(size_t)(l1+j)*ED];
                px[nxt][j] = xRow[(size_t)(l1+j)*ED];
                pz[nxt][j] = zRow[(size_t)(l1+j)*2*ED];
            }
        }
        #pragma unroll
        for (int j = 0; j < 4; j++) {
            const int li = (l0 & 127) + j;
            const float dv = pd[cur][j], xv = px[cur][j], zv = pz[cur][j];
            const float bx = dv * xv;

            float Bv[16], Cv[16];
            #pragma unroll
            for (int q = 0; q < 4; q++) {
                const float4 vb = *(const float4*)&sBC[li][q*4];
                Bv[q*4+0]=vb.x; Bv[q*4+1]=vb.y; Bv[q*4+2]=vb.z; Bv[q*4+3]=vb.w;
                const float4 vc = *(const float4*)&sBC[li][16 + q*4];
                Cv[q*4+0]=vc.x; Cv[q*4+1]=vc.y; Cv[q*4+2]=vc.z; Cv[q*4+3]=vc.w;
            }

            float dA[16];
            if (ok) {
                const float t1  = __expf(-dv);
                const float t2  = t1*t1;
                const float t3  = t2*t1;
                const float t4  = t2*t2;
                const float t8  = t4*t4;
                const float t12 = t8*t4;
                dA[0]=t1;      dA[1]=t2;      dA[2]=t3;      dA[3]=t4;
                dA[4]=t4*t1;   dA[5]=t4*t2;   dA[6]=t4*t3;   dA[7]=t8;
                dA[8]=t8*t1;   dA[9]=t8*t2;   dA[10]=t8*t3;  dA[11]=t12;
                dA[12]=t12*t1; dA[13]=t12*t2; dA[14]=t12*t3; dA[15]=t8*t8;
            } else {
                #pragma unroll
                for (int n = 0; n < 16; n++) dA[n] = __expf(dv * an[n]);
            }

            float y0=0.f, y1=0.f, y2=0.f, y3=0.f;
            #pragma unroll
            for (int n = 0; n < 4; n++) { h[n]    = dA[n]   *h[n]    + bx*Bv[n];    y0 += h[n]   *Cv[n];    }
            #pragma unroll
            for (int n = 4; n < 8; n++) { h[n]    = dA[n]   *h[n]    + bx*Bv[n];    y1 += h[n]   *Cv[n];    }
            #pragma unroll
            for (int n = 8; n < 12; n++){ h[n]    = dA[n]   *h[n]    + bx*Bv[n];    y2 += h[n]   *Cv[n];    }
            #pragma unroll
            for (int n = 12; n < 16; n++){h[n]    = dA[n]   *h[n]    + bx*Bv[n];    y3 += h[n]   *Cv[n];    }

            float yv = (y0 + y1) + (y2 + y3) + Dval * xv;
            const float sil = zv / (1.f + __expf(-zv));
            yv *= sil;

            const int l = l0 + j;
            const __nv_bfloat16 hh = __float2bfloat16(yv);
            yhRow[(size_t)l*ED] = hh;
            ylRow[(size_t)l*ED] = __float2bfloat16(yv - __bfloat162float(hh));
        }
    }
}

// ---------------- launch ---------------------------------------------------
extern "C" void kernel_launch(void* const* d_in, const int* in_sizes, int n_in,
                              void* d_out, int out_size)
{
    const float* x          = (const float*)d_in[0];  // (B,L,1024)
    const float* in_proj_w  = (const float*)d_in[1];  // (1024,4096)
    const float* conv_w     = (const float*)d_in[2];  // (2048,1,4)
    const float* conv_b     = (const float*)d_in[3];  // (2048,)
    const float* x_proj_w   = (const float*)d_in[4];  // (2048,96)
    const float* dt_proj_w  = (const float*)d_in[5];  // (64,2048)
    const float* dt_proj_b  = (const float*)d_in[6];  // (2048,)
    const float* A_log      = (const float*)d_in[7];  // (2048,16)
    const float* Dw         = (const float*)d_in[8];  // (2048,)
    const float* out_proj_w = (const float*)d_in[9];  // (2048,1024)
    float* out = (float*)d_out;                       // (B,L,1024)

    float *xzP, *xconvP, *dbcP, *deltaP;
    cudaGetSymbolAddress((void**)&xzP,    g_xz);
    cudaGetSymbolAddress((void**)&xconvP, g_xconv);
    cudaGetSymbolAddress((void**)&dbcP,   g_dbc);
    cudaGetSymbolAddress((void**)&deltaP, g_delta);

    __nv_bfloat16 *xhP, *xlP, *w1hP, *w1lP, *yhP, *ylP, *w6hP, *w6lP;
    cudaGetSymbolAddress((void**)&xhP,  g_xh);
    cudaGetSymbolAddress((void**)&xlP,  g_xl);
    cudaGetSymbolAddress((void**)&w1hP, g_w1h);
    cudaGetSymbolAddress((void**)&w1lP, g_w1l);
    cudaGetSymbolAddress((void**)&yhP,  g_yh);
    cudaGetSymbolAddress((void**)&ylP,  g_yl);
    cudaGetSymbolAddress((void**)&w6hP, g_w6h);
    cudaGetSymbolAddress((void**)&w6lP, g_w6l);

    cudaFuncSetAttribute(gemm_bf16x3,
                         cudaFuncAttributeMaxDynamicSharedMemorySize, GSM_BYTES);

    // 0) weight transpose + split
    wconv_kernel<<<dim3(2*ED/32, DMODEL/32), dim3(32,8)>>>(in_proj_w,  w1hP, w1lP, DMODEL, 2*ED);
    wconv_kernel<<<dim3(DMODEL/32, ED/32),   dim3(32,8)>>>(out_proj_w, w6hP, w6lP, ED, DMODEL);

    // 0b) x split
    aconv_kernel<<<(BL*DMODEL + 255)/256, 256>>>(x, xhP, xlP, BL*DMODEL);

    // 1) xz = x @ W1 : (2048 x 4096), K=1024 — bf16x3 mma.sync
    gemm_bf16x3<<<dim3(2*ED/128, BL/128), 256, GSM_BYTES>>>(
        xhP, xlP, w1hP, w1lP, xzP, BL, 2*ED, DMODEL);

    // 2) depthwise causal conv + SiLU -> xconv
    conv_silu_kernel<<<(BB*LL*ED + 255)/256, 256>>>(xzP, conv_w, conv_b, xconvP);

    // 3) dbc = xconv @ x_proj_w : (2048 x 96), K=2048
    {
        dim3 grid(2, BL/32);
        sgemm_kernel<32,48,32,2,6,0><<<grid, 128>>>(
            xconvP, x_proj_w, dbcP, BL, 96, ED, ED, 96, 96, nullptr);
    }

    // 4) delta = softplus(dbc[:, :64] @ dt_proj_w + b) : (2048 x 2048), K=64
    {
        dim3 grid(ED/64, BL/64);
        sgemm_kernel<64,64,16,4,4,1><<<grid, 256>>>(
            dbcP, dt_proj_w, deltaP, BL, ED, DTRANK, 96, ED, ED, dt_proj_b);
    }

    // 5) fused selective scan v2 -> yh/yl bf16 split directly
    {
        dim3 grid(ED/32, BB);
        scan2_kernel<<<grid, 32>>>(deltaP, dbcP, xconvP, xzP, A_log, Dw, yhP, ylP);
    }

    // 6) out = y @ W6 : (2048 x 1024), K=2048 — bf16x3 mma.sync
    gemm_bf16x3<<<dim3(DMODEL/128, BL/128), 256, GSM_BYTES>>>(
        yhP, ylP, w6hP, w6lP, out, BL, DMODEL, ED);
}

// round 7
// speedup vs baseline: 2.1911x; 1.0270x over previous
#include <cuda_runtime.h>
#include <cuda_bf16.h>
#include <cstdint>

// ---------------- problem constants ----------------------------------------
#define BB 2
#define LL 1024
#define DMODEL 1024
#define ED 2048
#define NSTATE 16
#define DTRANK 64
#define BL (BB*LL)          // 2048 rows

// ---------------- scratch (no allocation allowed -> __device__ globals) ----
__device__ __align__(128) float g_xz[BB*LL*2*ED];      // (B,L,4096)
__device__ __align__(128) float g_xconv[BB*LL*ED];     // (B,L,2048)
__device__ __align__(128) float g_dbc[BL*96];          // (BL,96)
__device__ __align__(128) float g_delta[BB*LL*ED];     // (B,L,2048)

// bf16 split-precision scratch
__device__ __align__(128) __nv_bfloat16 g_xh[BL*DMODEL];
__device__ __align__(128) __nv_bfloat16 g_xl[BL*DMODEL];
__device__ __align__(128) __nv_bfloat16 g_w1h[2*ED*DMODEL];
__device__ __align__(128) __nv_bfloat16 g_w1l[2*ED*DMODEL];
__device__ __align__(128) __nv_bfloat16 g_yh[BL*ED];
__device__ __align__(128) __nv_bfloat16 g_yl[BL*ED];
__device__ __align__(128) __nv_bfloat16 g_w6h[DMODEL*ED];
__device__ __align__(128) __nv_bfloat16 g_w6l[DMODEL*ED];

// ---------------- PTX helpers (sm_80-level only: no tcgen05/TMA!) ----------
__device__ __forceinline__ uint32_t smem_u32(const void* p) {
    uint32_t a;
    asm("{ .reg .u64 t; cvta.to.shared.u64 t, %1; cvt.u32.u64 %0, t; }"
        : "=r"(a) : "l"(p));
    return a;
}

#define CP_ASYNC16(dst, src) \
    asm volatile("cp.async.cg.shared.global [%0], [%1], 16;" \
                 :: "r"(dst), "l"(src) : "memory")
#define CP_COMMIT() asm volatile("cp.async.commit_group;" ::: "memory")
#define CP_WAIT(n)  asm volatile("cp.async.wait_group %0;" :: "n"(n) : "memory")

#define LDSM_X4(r0,r1,r2,r3, addr) \
    asm volatile("ldmatrix.sync.aligned.m8n8.x4.shared.b16 {%0,%1,%2,%3}, [%4];" \
                 : "=r"(r0),"=r"(r1),"=r"(r2),"=r"(r3) : "r"(addr))

__device__ __forceinline__ void mma_bf16(float* c, const uint32_t* a, const uint32_t* b) {
    asm volatile(
        "mma.sync.aligned.m16n8k16.row.col.f32.bf16.bf16.f32 "
        "{%0,%1,%2,%3}, {%4,%5,%6,%7}, {%8,%9}, {%0,%1,%2,%3};"
        : "+f"(c[0]), "+f"(c[1]), "+f"(c[2]), "+f"(c[3])
        : "r"(a[0]), "r"(a[1]), "r"(a[2]), "r"(a[3]), "r"(b[0]), "r"(b[1]));
}

// ---------------- bf16x3 mma.sync GEMM: C(M,N) = A(M,K) * Bt(N,K)^T --------
// CTA 128x128, BK=32, 8 warps of 64x32. 3-stage cp.async pipeline.
#define TPAD 40                          // bf16 elems per smem row (80 B)
#define TILE_B (128*TPAD*2)              // 10240 B per tile
#define STAGE_B (4*TILE_B)               // Ah,Al,Bh,Bl
#define GSM_BYTES (3*STAGE_B)            // 122880 B

__global__ __launch_bounds__(256, 1)
void gemm_bf16x3(const __nv_bfloat16* __restrict__ Ah, const __nv_bfloat16* __restrict__ Al,
                 const __nv_bfloat16* __restrict__ Bh, const __nv_bfloat16* __restrict__ Bl,
                 float* __restrict__ C, int M, int N, int K)
{
    extern __shared__ __align__(128) char smem[];
    const uint32_t sb = smem_u32(smem);
    const int tid  = threadIdx.x;
    const int lane = tid & 31;
    const int warp = tid >> 5;
    const int wm   = warp >> 2;          // 0..1  (M)
    const int wn   = warp & 3;           // 0..3  (N)
    const int m0 = blockIdx.y * 128, n0 = blockIdx.x * 128;
    const int NK = K >> 5;               // K/32 chunks

    const __nv_bfloat16* gbase[4] = {
        Ah + (size_t)m0 * K, Al + (size_t)m0 * K,
        Bh + (size_t)n0 * K, Bl + (size_t)n0 * K };

    auto loadStage = [&](int kc) {
        const uint32_t stg = sb + (uint32_t)(kc % 3) * STAGE_B;
        const int koff = kc * 32;
        #pragma unroll
        for (int i = 0; i < 8; i++) {
            const int c  = tid + i * 256;
            const int t  = c >> 9;
            const int cc = c & 511;
            const int row = cc >> 2, q = cc & 3;
            const __nv_bfloat16* src = gbase[t] + (size_t)row * K + koff + q * 8;
            const uint32_t dst = stg + t * TILE_B + (row * TPAD + q * 8) * 2;
            CP_ASYNC16(dst, src);
        }
    };

    float acc[4][4][4];
    #pragma unroll
    for (int i = 0; i < 4; i++)
        #pragma unroll
        for (int j = 0; j < 4; j++)
            #pragma unroll
            for (int k = 0; k < 4; k++) acc[i][j][k] = 0.f;

    // A ldmatrix x4: lane&15 -> row, lane>>4 -> 16B k-half
    const uint32_t aRow = (uint32_t)(wm * 64 + (lane & 15)) * (TPAD * 2)
                        + (uint32_t)(lane >> 4) * 16;
    // B ldmatrix x4 (nf pairs): g=lane>>3 -> (nf_in_pair=g>>1, khalf=g&1)
    const uint32_t bRow = (uint32_t)(wn * 32 + ((lane >> 4) & 1) * 8 + (lane & 7)) * (TPAD * 2)
                        + (uint32_t)((lane >> 3) & 1) * 16;

    loadStage(0); CP_COMMIT();
    loadStage(1); CP_COMMIT();

    for (int kc = 0; kc < NK; kc++) {
        CP_WAIT(1);
        __syncthreads();

        // issue loads for kc+2 into buffer freed by the barrier
        if (kc + 2 < NK) loadStage(kc + 2);
        CP_COMMIT();

        const uint32_t stg = sb + (uint32_t)(kc % 3) * STAGE_B;
        const uint32_t sAh = stg,            sAl = stg + TILE_B;
        const uint32_t sBh = stg + 2*TILE_B, sBl = stg + 3*TILE_B;

        #pragma unroll
        for (int ks = 0; ks < 2; ks++) {
            const uint32_t kOff = ks * 32;

            uint32_t ah[4][4], al[4][4], bh[4][2], bl[4][2];
            #pragma unroll
            for (int mf = 0; mf < 4; mf++) {
                const uint32_t ro = aRow + (uint32_t)mf * 16 * (TPAD * 2) + kOff;
                LDSM_X4(ah[mf][0], ah[mf][1], ah[mf][2], ah[mf][3], sAh + ro);
                LDSM_X4(al[mf][0], al[mf][1], al[mf][2], al[mf][3], sAl + ro);
            }
            #pragma unroll
            for (int p = 0; p < 2; p++) {
                const uint32_t ro = bRow + (uint32_t)p * 16 * (TPAD * 2) + kOff;
                LDSM_X4(bh[2*p][0], bh[2*p][1], bh[2*p+1][0], bh[2*p+1][1], sBh + ro);
                LDSM_X4(bl[2*p][0], bl[2*p][1], bl[2*p+1][0], bl[2*p+1][1], sBl + ro);
            }
            #pragma unroll
            for (int mf = 0; mf < 4; mf++)
                #pragma unroll
                for (int nf = 0; nf < 4; nf++) {
                    mma_bf16(acc[mf][nf], ah[mf], bh[nf]);
                    mma_bf16(acc[mf][nf], ah[mf], bl[nf]);
                    mma_bf16(acc[mf][nf], al[mf], bh[nf]);
                }
        }
    }

    const int mBase = m0 + wm * 64 + (lane >> 2);
    const int nBase = n0 + wn * 32 + (lane & 3) * 2;
    #pragma unroll
    for (int mf = 0; mf < 4; mf++)
        #pragma unroll
        for (int nf = 0; nf < 4; nf++) {
            const int r = mBase + mf * 16;
            const int c = nBase + nf * 8;
            *(float2*)&C[(size_t)r * N + c]       = make_float2(acc[mf][nf][0], acc[mf][nf][1]);
            *(float2*)&C[(size_t)(r + 8) * N + c] = make_float2(acc[mf][nf][2], acc[mf][nf][3]);
        }
}

// ---------------- weight transpose + bf16 hi/lo split ----------------------
__global__ void wconv_kernel(const float* __restrict__ W,
                             __nv_bfloat16* __restrict__ Th,
                             __nv_bfloat16* __restrict__ Tl, int K, int N)
{
    __shared__ float t[32][33];
    const int bx = blockIdx.x * 32;  // n
    const int by = blockIdx.y * 32;  // k
    const int tx = threadIdx.x, ty = threadIdx.y;
    #pragma unroll
    for (int j = 0; j < 32; j += 8)
        t[ty + j][tx] = W[(size_t)(by + ty + j) * N + bx + tx];
    __syncthreads();
    #pragma unroll
    for (int j = 0; j < 32; j += 8) {
        const float v = t[tx][ty + j];
        const __nv_bfloat16 h = __float2bfloat16(v);
        const float r = v - __bfloat162float(h);
        const size_t o = (size_t)(bx + ty + j) * K + by + tx;
        Th[o] = h;  Tl[o] = __float2bfloat16(r);
    }
}

// ---------------- activation bf16 hi/lo split ------------------------------
__global__ void aconv_kernel(const float* __restrict__ A,
                             __nv_bfloat16* __restrict__ H,
                             __nv_bfloat16* __restrict__ L, int n)
{
    const int i = blockIdx.x * blockDim.x + threadIdx.x;
    if (i >= n) return;
    const float v = A[i];
    const __nv_bfloat16 h = __float2bfloat16(v);
    H[i] = h;
    L[i] = __float2bfloat16(v - __bfloat162float(h));
}

// ---------------- fp32 SIMT SGEMM (small GEMMs) ----------------------------
template<int BM,int BN,int BK,int TM,int TN,int ACT>
__global__ void sgemm_kernel(const float* __restrict__ A,
                             const float* __restrict__ Bm,
                             float* __restrict__ C,
                             int M, int N, int K,
                             int lda, int ldb, int ldc,
                             const float* __restrict__ bias)
{
    constexpr int THREADS = (BM/TM)*(BN/TN);
    __shared__ float As[BK][BM];
    __shared__ float Bs[BK][BN];

    const int tid = threadIdx.x;
    const int tx  = tid % (BN/TN);
    const int ty  = tid / (BN/TN);
    const int rowBase = blockIdx.y * BM;
    const int colBase = blockIdx.x * BN;

    float acc[TM][TN];
    #pragma unroll
    for (int i = 0; i < TM; i++)
        #pragma unroll
        for (int j = 0; j < TN; j++) acc[i][j] = 0.f;

    constexpr int A_LOADS = (BM*BK/4) / THREADS;
    constexpr int B_LOADS = (BK*BN/4) / THREADS;
    static_assert(A_LOADS*THREADS == BM*BK/4, "A tile not divisible");
    static_assert(B_LOADS*THREADS == BK*BN/4, "B tile not divisible");

    for (int k0 = 0; k0 < K; k0 += BK) {
        #pragma unroll
        for (int i = 0; i < A_LOADS; i++) {
            int idx = tid + i*THREADS;
            int r  = idx / (BK/4);
            int c4 = idx % (BK/4);
            float4 v = *(const float4*)&A[(size_t)(rowBase + r)*lda + k0 + c4*4];
            As[c4*4+0][r] = v.x;
            As[c4*4+1][r] = v.y;
            As[c4*4+2][r] = v.z;
            As[c4*4+3][r] = v.w;
        }
        #pragma unroll
        for (int i = 0; i < B_LOADS; i++) {
            int idx = tid + i*THREADS;
            int r  = idx / (BN/4);
            int c4 = idx % (BN/4);
            *(float4*)&Bs[r][c4*4] =
                *(const float4*)&Bm[(size_t)(k0 + r)*ldb + colBase + c4*4];
        }
        __syncthreads();

        #pragma unroll
        for (int k = 0; k < BK; k++) {
            float ra[TM], rb[TN];
            #pragma unroll
            for (int i = 0; i < TM; i++) ra[i] = As[k][ty*TM + i];
            #pragma unroll
            for (int j = 0; j < TN; j++) rb[j] = Bs[k][tx*TN + j];
            #pragma unroll
            for (int i = 0; i < TM; i++)
                #pragma unroll
                for (int j = 0; j < TN; j++)
                    acc[i][j] += ra[i]*rb[j];
        }
        __syncthreads();
    }

    #pragma unroll
    for (int i = 0; i < TM; i++) {
        int r = rowBase + ty*TM + i;
        #pragma unroll
        for (int j = 0; j < TN; j++) {
            int c = colBase + tx*TN + j;
            float v = acc[i][j];
            if (ACT == 1) {
                v += bias[c];
                v = (v > 20.f) ? v : log1pf(expf(v));
            }
            C[(size_t)r*ldc + c] = v;
        }
    }
}

// ---------------- depthwise causal conv1d (K=4) + bias + SiLU --------------
__global__ void conv_silu_kernel(const float* __restrict__ xz,
                                 const float* __restrict__ w,
                                 const float* __restrict__ bias,
                                 float* __restrict__ out)
{
    int idx = blockIdx.x*blockDim.x + threadIdx.x;
    if (idx >= BB*LL*ED) return;
    int e = idx % ED;
    int l = (idx / ED) % LL;
    int b = idx / (ED*LL);

    const float4 wv = *(const float4*)&w[e*4];
    const float* base = xz + (size_t)b*LL*2*ED + e;

    float s = bias[e];
    if (l >= 3) s += wv.x * base[(size_t)(l-3)*2*ED];
    if (l >= 2) s += wv.y * base[(size_t)(l-2)*2*ED];
    if (l >= 1) s += wv.z * base[(size_t)(l-1)*2*ED];
    s += wv.w * base[(size_t)l*2*ED];

    out[idx] = s / (1.f + __expf(-s));
}

// ---------------- fused selective scan v2: thread-per-e, 16 states in regs -
__global__ __launch_bounds__(32)
void scan2_kernel(const float* __restrict__ delta,  // (B,L,ED)
                  const float* __restrict__ dbc,    // (BL,96)
                  const float* __restrict__ xconv,  // (B,L,ED)
                  const float* __restrict__ xz,     // (B,L,2ED), z at +ED
                  const float* __restrict__ A_log,  // (ED,16)
                  const float* __restrict__ Dw,     // (ED,)
                  __nv_bfloat16* __restrict__ yh,
                  __nv_bfloat16* __restrict__ yl)
{
    const int b   = blockIdx.y;
    const int tid = threadIdx.x;
    const int e   = blockIdx.x * 32 + tid;

    __shared__ __align__(16) float sBC[128][36];   // [li][0..15]=B, [16..31]=C

    float an[16];
    bool ok = true;
    #pragma unroll
    for (int n = 0; n < 16; n++) {
        an[n] = -__expf(A_log[e*NSTATE + n]);
        ok = ok && (fabsf(an[n] + (float)(n+1)) < 1e-4f * (float)(n+1));
    }
    const float Dval = Dw[e];

    const float* dRow   = delta + (size_t)b*LL*ED + e;
    const float* xRow   = xconv + (size_t)b*LL*ED + e;
    const float* zRow   = xz    + (size_t)b*LL*2*ED + ED + e;
    const float* bcBase = dbc   + (size_t)b*LL*96;
    __nv_bfloat16* yhRow = yh + (size_t)b*LL*ED + e;
    __nv_bfloat16* ylRow = yl + (size_t)b*LL*ED + e;

    float h[16];
    #pragma unroll
    for (int n = 0; n < 16; n++) h[n] = 0.f;

    float pd[2][4], px[2][4], pz[2][4];
    #pragma unroll
    for (int j = 0; j < 4; j++) {
        pd[0][j] = dRow[(size_t)j*ED];
        px[0][j] = xRow[(size_t)j*ED];
        pz[0][j] = zRow[(size_t)j*2*ED];
    }

    for (int g = 0; g < LL/4; g++) {
        const int l0 = g * 4;
        if ((l0 & 127) == 0) {
            __syncwarp();
            for (int i = tid; i < 128*8; i += 32) {
                const int li = i >> 3, q = i & 7;
                const float4 v = *(const float4*)&bcBase[(size_t)(l0+li)*96 + DTRANK + q*4];
                *(float4*)&sBC[li][q*4] = v;
            }
            __syncwarp();
        }
        const int cur = g & 1, nxt = cur ^ 1;
        if (g + 1 < LL/4) {
            const int l1 = l0 + 4;
            #pragma unroll
            for (int j = 0; j < 4; j++) {
                pd[nxt][j] = dRow[(size_t)(l1+j)*ED];
                px[nxt][j] = xRow[(size_t)(l1+j)*ED];
                pz[nxt][j] = zRow[(size_t)(l1+j)*2*ED];
            }
        }
        #pragma unroll
        for (int j = 0; j < 4; j++) {
            const int li = (l0 & 127) + j;
            const float dv = pd[cur][j], xv = px[cur][j], zv = pz[cur][j];
            const float bx = dv * xv;

            float Bv[16], Cv[16];
            #pragma unroll
            for (int q = 0; q < 4; q++) {
                const float4 vb = *(const float4*)&sBC[li][q*4];
                Bv[q*4+0]=vb.x; Bv[q*4+1]=vb.y; Bv[q*4+2]=vb.z; Bv[q*4+3]=vb.w;
                const float4 vc = *(const float4*)&sBC[li][16 + q*4];
                Cv[q*4+0]=vc.x; Cv[q*4+1]=vc.y; Cv[q*4+2]=vc.z; Cv[q*4+3]=vc.w;
            }

            float dA[16];
            if (ok) {
                const float t1  = __expf(-dv);
                const float t2  = t1*t1;
                const float t3  = t2*t1;
                const float t4  = t2*t2;
                const float t8  = t4*t4;
                const float t12 = t8*t4;
                dA[0]=t1;      dA[1]=t2;      dA[2]=t3;      dA[3]=t4;
                dA[4]=t4*t1;   dA[5]=t4*t2;   dA[6]=t4*t3;   dA[7]=t8;
                dA[8]=t8*t1;   dA[9]=t8*t2;   dA[10]=t8*t3;  dA[11]=t12;
                dA[12]=t12*t1; dA[13]=t12*t2; dA[14]=t12*t3; dA[15]=t8*t8;
            } else {
                #pragma unroll
                for (int n = 0; n < 16; n++) dA[n] = __expf(dv * an[n]);
            }

            float y0=0.f, y1=0.f, y2=0.f, y3=0.f;
            #pragma unroll
            for (int n = 0; n < 4; n++) { h[n] = dA[n]*h[n] + bx*Bv[n]; y0 += h[n]*Cv[n]; }
            #pragma unroll
            for (int n = 4; n < 8; n++) { h[n] = dA[n]*h[n] + bx*Bv[n]; y1 += h[n]*Cv[n]; }
            #pragma unroll
            for (int n = 8; n < 12; n++){ h[n] = dA[n]*h[n] + bx*Bv[n]; y2 += h[n]*Cv[n]; }
            #pragma unroll
            for (int n = 12; n < 16; n++){h[n] = dA[n]*h[n] + bx*Bv[n]; y3 += h[n]*Cv[n]; }

            float yv = (y0 + y1) + (y2 + y3) + Dval * xv;
            const float sil = zv / (1.f + __expf(-zv));
            yv *= sil;

            const int l = l0 + j;
            const __nv_bfloat16 hh = __float2bfloat16(yv);
            yhRow[(size_t)l*ED] = hh;
            ylRow[(size_t)l*ED] = __float2bfloat16(yv - __bfloat162float(hh));
        }
    }
}

// ---------------- launch ---------------------------------------------------
extern "C" void kernel_launch(void* const* d_in, const int* in_sizes, int n_in,
                              void* d_out, int out_size)
{
    const float* x          = (const float*)d_in[0];  // (B,L,1024)
    const float* in_proj_w  = (const float*)d_in[1];  // (1024,4096)
    const float* conv_w     = (const float*)d_in[2];  // (2048,1,4)
    const float* conv_b     = (const float*)d_in[3];  // (2048,)
    const float* x_proj_w   = (const float*)d_in[4];  // (2048,96)
    const float* dt_proj_w  = (const float*)d_in[5];  // (64,2048)
    const float* dt_proj_b  = (const float*)d_in[6];  // (2048,)
    const float* A_log      = (const float*)d_in[7];  // (2048,16)
    const float* Dw         = (const float*)d_in[8];  // (2048,)
    const float* out_proj_w = (const float*)d_in[9];  // (2048,1024)
    float* out = (float*)d_out;                       // (B,L,1024)

    float *xzP, *xconvP, *dbcP, *deltaP;
    cudaGetSymbolAddress((void**)&xzP,    g_xz);
    cudaGetSymbolAddress((void**)&xconvP, g_xconv);
    cudaGetSymbolAddress((void**)&dbcP,   g_dbc);
    cudaGetSymbolAddress((void**)&deltaP, g_delta);

    __nv_bfloat16 *xhP, *xlP, *w1hP, *w1lP, *yhP, *ylP, *w6hP, *w6lP;
    cudaGetSymbolAddress((void**)&xhP,  g_xh);
    cudaGetSymbolAddress((void**)&xlP,  g_xl);
    cudaGetSymbolAddress((void**)&w1hP, g_w1h);
    cudaGetSymbolAddress((void**)&w1lP, g_w1l);
    cudaGetSymbolAddress((void**)&yhP,  g_yh);
    cudaGetSymbolAddress((void**)&ylP,  g_yl);
    cudaGetSymbolAddress((void**)&w6hP, g_w6h);
    cudaGetSymbolAddress((void**)&w6lP, g_w6l);

    cudaFuncSetAttribute(gemm_bf16x3,
                         cudaFuncAttributeMaxDynamicSharedMemorySize, GSM_BYTES);

    // 0) weight transpose + split
    wconv_kernel<<<dim3(2*ED/32, DMODEL/32), dim3(32,8)>>>(in_proj_w,  w1hP, w1lP, DMODEL, 2*ED);
    wconv_kernel<<<dim3(DMODEL/32, ED/32),   dim3(32,8)>>>(out_proj_w, w6hP, w6lP, ED, DMODEL);

    // 0b) x split
    aconv_kernel<<<(BL*DMODEL + 255)/256, 256>>>(x, xhP, xlP, BL*DMODEL);

    // 1) xz = x @ W1 : (2048 x 4096), K=1024 — bf16x3 mma.sync
    gemm_bf16x3<<<dim3(2*ED/128, BL/128), 256, GSM_BYTES>>>(
        xhP, xlP, w1hP, w1lP, xzP, BL, 2*ED, DMODEL);

    // 2) depthwise causal conv + SiLU -> xconv
    conv_silu_kernel<<<(BB*LL*ED + 255)/256, 256>>>(xzP, conv_w, conv_b, xconvP);

    // 3) dbc = xconv @ x_proj_w : (2048 x 96), K=2048
    {
        dim3 grid(2, BL/32);
        sgemm_kernel<32,48,32,2,6,0><<<grid, 128>>>(
            xconvP, x_proj_w, dbcP, BL, 96, ED, ED, 96, 96, nullptr);
    }

    // 4) delta = softplus(dbc[:, :64] @ dt_proj_w + b) : (2048 x 2048), K=64
    {
        dim3 grid(ED/64, BL/64);
        sgemm_kernel<64,64,16,4,4,1><<<grid, 256>>>(
            dbcP, dt_proj_w, deltaP, BL, ED, DTRANK, 96, ED, ED, dt_proj_b);
    }

    // 5) fused selective scan v2 -> yh/yl bf16 split directly
    {
        dim3 grid(ED/32, BB);
        scan2_kernel<<<grid, 32>>>(deltaP, dbcP, xconvP, xzP, A_log, Dw, yhP, ylP);
    }

    // 6) out = y @ W6 : (2048 x 1024), K=2048 — bf16x3 mma.sync
    gemm_bf16x3<<<dim3(DMODEL/128, BL/128), 256, GSM_BYTES>>>(
        yhP, ylP, w6hP, w6lP, out, BL, DMODEL, ED);
}

// round 8
// speedup vs baseline: 2.2560x; 1.0297x over previous
#include <cuda_runtime.h>
#include <cuda_bf16.h>
#include <cstdint>

// ---------------- problem constants ----------------------------------------
#define BB 2
#define LL 1024
#define DMODEL 1024
#define ED 2048
#define NSTATE 16
#define DTRANK 64
#define BL (BB*LL)          // 2048 rows

// ---------------- scratch (no allocation allowed -> __device__ globals) ----
__device__ __align__(128) float g_xz[BB*LL*2*ED];      // (B,L,4096)
__device__ __align__(128) float g_xconv[BB*LL*ED];     // (B,L,2048)
__device__ __align__(128) float g_dbc[BL*96];          // (BL,96)
__device__ __align__(128) float g_delta[BB*LL*ED];     // (B,L,2048)

// bf16 split-precision scratch
__device__ __align__(128) __nv_bfloat16 g_xh[BL*DMODEL];
__device__ __align__(128) __nv_bfloat16 g_xl[BL*DMODEL];
__device__ __align__(128) __nv_bfloat16 g_w1h[2*ED*DMODEL];
__device__ __align__(128) __nv_bfloat16 g_w1l[2*ED*DMODEL];
__device__ __align__(128) __nv_bfloat16 g_yh[BL*ED];
__device__ __align__(128) __nv_bfloat16 g_yl[BL*ED];
__device__ __align__(128) __nv_bfloat16 g_w6h[DMODEL*ED];
__device__ __align__(128) __nv_bfloat16 g_w6l[DMODEL*ED];

// ---------------- PTX helpers (sm_80-level only: no tcgen05/TMA!) ----------
__device__ __forceinline__ uint32_t smem_u32(const void* p) {
    uint32_t a;
    asm("{ .reg .u64 t; cvta.to.shared.u64 t, %1; cvt.u32.u64 %0, t; }"
        : "=r"(a) : "l"(p));
    return a;
}

#define CP_ASYNC16(dst, src) \
    asm volatile("cp.async.cg.shared.global [%0], [%1], 16;" \
                 :: "r"(dst), "l"(src) : "memory")
#define CP_COMMIT() asm volatile("cp.async.commit_group;" ::: "memory")
#define CP_WAIT(n)  asm volatile("cp.async.wait_group %0;" :: "n"(n) : "memory")

#define LDSM_X4(r0,r1,r2,r3, addr) \
    asm volatile("ldmatrix.sync.aligned.m8n8.x4.shared.b16 {%0,%1,%2,%3}, [%4];" \
                 : "=r"(r0),"=r"(r1),"=r"(r2),"=r"(r3) : "r"(addr))

__device__ __forceinline__ void mma_bf16(float* c, const uint32_t* a, const uint32_t* b) {
    asm volatile(
        "mma.sync.aligned.m16n8k16.row.col.f32.bf16.bf16.f32 "
        "{%0,%1,%2,%3}, {%4,%5,%6,%7}, {%8,%9}, {%0,%1,%2,%3};"
        : "+f"(c[0]), "+f"(c[1]), "+f"(c[2]), "+f"(c[3])
        : "r"(a[0]), "r"(a[1]), "r"(a[2]), "r"(a[3]), "r"(b[0]), "r"(b[1]));
}

// ---------------- bf16x3 mma.sync GEMM: C(M,N) = A(M,K) * Bt(N,K)^T --------
// CTA 128x128, BK=32, 8 warps of 64x32. 2-stage pipeline, 2 CTAs/SM.
#define TPAD 40                          // bf16 elems per smem row (80 B)
#define TILE_B (128*TPAD*2)              // 10240 B per tile
#define STAGE_B (4*TILE_B)               // Ah,Al,Bh,Bl
#define GSM_BYTES (2*STAGE_B)            // 81920 B

__global__ __launch_bounds__(256, 2)
void gemm_bf16x3(const __nv_bfloat16* __restrict__ Ah, const __nv_bfloat16* __restrict__ Al,
                 const __nv_bfloat16* __restrict__ Bh, const __nv_bfloat16* __restrict__ Bl,
                 float* __restrict__ C, int M, int N, int K)
{
    extern __shared__ __align__(128) char smem[];
    const uint32_t sb = smem_u32(smem);
    const int tid  = threadIdx.x;
    const int lane = tid & 31;
    const int warp = tid >> 5;
    const int wm   = warp >> 2;          // 0..1  (M)
    const int wn   = warp & 3;           // 0..3  (N)
    const int m0 = blockIdx.y * 128, n0 = blockIdx.x * 128;
    const int NK = K >> 5;               // K/32 chunks

    const __nv_bfloat16* gbase[4] = {
        Ah + (size_t)m0 * K, Al + (size_t)m0 * K,
        Bh + (size_t)n0 * K, Bl + (size_t)n0 * K };

    auto loadStage = [&](int kc) {
        const uint32_t stg = sb + (uint32_t)(kc & 1) * STAGE_B;
        const int koff = kc * 32;
        #pragma unroll
        for (int i = 0; i < 8; i++) {
            const int c  = tid + i * 256;
            const int t  = c >> 9;
            const int cc = c & 511;
            const int row = cc >> 2, q = cc & 3;
            const __nv_bfloat16* src = gbase[t] + (size_t)row * K + koff + q * 8;
            const uint32_t dst = stg + t * TILE_B + (row * TPAD + q * 8) * 2;
            CP_ASYNC16(dst, src);
        }
    };

    float acc[4][4][4];
    #pragma unroll
    for (int i = 0; i < 4; i++)
        #pragma unroll
        for (int j = 0; j < 4; j++)
            #pragma unroll
            for (int k = 0; k < 4; k++) acc[i][j][k] = 0.f;

    // A ldmatrix x4: lane&15 -> row, lane>>4 -> 16B k-half
    const uint32_t aRow = (uint32_t)(wm * 64 + (lane & 15)) * (TPAD * 2)
                        + (uint32_t)(lane >> 4) * 16;
    // B ldmatrix x4 (nf pairs)
    const uint32_t bRow = (uint32_t)(wn * 32 + ((lane >> 4) & 1) * 8 + (lane & 7)) * (TPAD * 2)
                        + (uint32_t)((lane >> 3) & 1) * 16;

    loadStage(0);
    CP_COMMIT();

    for (int kc = 0; kc < NK; kc++) {
        if (kc + 1 < NK) { loadStage(kc + 1); CP_COMMIT(); CP_WAIT(1); }
        else             { CP_WAIT(0); }
        __syncthreads();

        const uint32_t stg = sb + (uint32_t)(kc & 1) * STAGE_B;
        const uint32_t sAh = stg,            sAl = stg + TILE_B;
        const uint32_t sBh = stg + 2*TILE_B, sBl = stg + 3*TILE_B;

        #pragma unroll
        for (int ks = 0; ks < 2; ks++) {
            const uint32_t kOff = ks * 32;

            uint32_t bh[4][2], bl[4][2];
            #pragma unroll
            for (int p = 0; p < 2; p++) {
                const uint32_t ro = bRow + (uint32_t)p * 16 * (TPAD * 2) + kOff;
                LDSM_X4(bh[2*p][0], bh[2*p][1], bh[2*p+1][0], bh[2*p+1][1], sBh + ro);
                LDSM_X4(bl[2*p][0], bl[2*p][1], bl[2*p+1][0], bl[2*p+1][1], sBl + ro);
            }
            #pragma unroll
            for (int mf = 0; mf < 4; mf++) {
                const uint32_t ro = aRow + (uint32_t)mf * 16 * (TPAD * 2) + kOff;
                uint32_t ah[4], al[4];
                LDSM_X4(ah[0], ah[1], ah[2], ah[3], sAh + ro);
                LDSM_X4(al[0], al[1], al[2], al[3], sAl + ro);
                #pragma unroll
                for (int nf = 0; nf < 4; nf++) {
                    mma_bf16(acc[mf][nf], ah, bh[nf]);
                    mma_bf16(acc[mf][nf], ah, bl[nf]);
                    mma_bf16(acc[mf][nf], al, bh[nf]);
                }
            }
        }
        __syncthreads();
    }

    const int mBase = m0 + wm * 64 + (lane >> 2);
    const int nBase = n0 + wn * 32 + (lane & 3) * 2;
    #pragma unroll
    for (int mf = 0; mf < 4; mf++)
        #pragma unroll
        for (int nf = 0; nf < 4; nf++) {
            const int r = mBase + mf * 16;
            const int c = nBase + nf * 8;
            *(float2*)&C[(size_t)r * N + c]       = make_float2(acc[mf][nf][0], acc[mf][nf][1]);
            *(float2*)&C[(size_t)(r + 8) * N + c] = make_float2(acc[mf][nf][2], acc[mf][nf][3]);
        }
}

// ---------------- weight transpose + bf16 hi/lo split ----------------------
__global__ void wconv_kernel(const float* __restrict__ W,
                             __nv_bfloat16* __restrict__ Th,
                             __nv_bfloat16* __restrict__ Tl, int K, int N)
{
    __shared__ float t[32][33];
    const int bx = blockIdx.x * 32;  // n
    const int by = blockIdx.y * 32;  // k
    const int tx = threadIdx.x, ty = threadIdx.y;
    #pragma unroll
    for (int j = 0; j < 32; j += 8)
        t[ty + j][tx] = W[(size_t)(by + ty + j) * N + bx + tx];
    __syncthreads();
    #pragma unroll
    for (int j = 0; j < 32; j += 8) {
        const float v = t[tx][ty + j];
        const __nv_bfloat16 h = __float2bfloat16(v);
        const float r = v - __bfloat162float(h);
        const size_t o = (size_t)(bx + ty + j) * K + by + tx;
        Th[o] = h;  Tl[o] = __float2bfloat16(r);
    }
}

// ---------------- activation bf16 hi/lo split ------------------------------
__global__ void aconv_kernel(const float* __restrict__ A,
                             __nv_bfloat16* __restrict__ H,
                             __nv_bfloat16* __restrict__ L, int n)
{
    const int i = blockIdx.x * blockDim.x + threadIdx.x;
    if (i >= n) return;
    const float v = A[i];
    const __nv_bfloat16 h = __float2bfloat16(v);
    H[i] = h;
    L[i] = __float2bfloat16(v - __bfloat162float(h));
}

// ---------------- fp32 SIMT SGEMM (small GEMMs) ----------------------------
template<int BM,int BN,int BK,int TM,int TN,int ACT>
__global__ void sgemm_kernel(const float* __restrict__ A,
                             const float* __restrict__ Bm,
                             float* __restrict__ C,
                             int M, int N, int K,
                             int lda, int ldb, int ldc,
                             const float* __restrict__ bias)
{
    constexpr int THREADS = (BM/TM)*(BN/TN);
    __shared__ float As[BK][BM];
    __shared__ float Bs[BK][BN];

    const int tid = threadIdx.x;
    const int tx  = tid % (BN/TN);
    const int ty  = tid / (BN/TN);
    const int rowBase = blockIdx.y * BM;
    const int colBase = blockIdx.x * BN;

    float acc[TM][TN];
    #pragma unroll
    for (int i = 0; i < TM; i++)
        #pragma unroll
        for (int j = 0; j < TN; j++) acc[i][j] = 0.f;

    constexpr int A_LOADS = (BM*BK/4) / THREADS;
    constexpr int B_LOADS = (BK*BN/4) / THREADS;
    static_assert(A_LOADS*THREADS == BM*BK/4, "A tile not divisible");
    static_assert(B_LOADS*THREADS == BK*BN/4, "B tile not divisible");

    for (int k0 = 0; k0 < K; k0 += BK) {
        #pragma unroll
        for (int i = 0; i < A_LOADS; i++) {
            int idx = tid + i*THREADS;
            int r  = idx / (BK/4);
            int c4 = idx % (BK/4);
            float4 v = *(const float4*)&A[(size_t)(rowBase + r)*lda + k0 + c4*4];
            As[c4*4+0][r] = v.x;
            As[c4*4+1][r] = v.y;
            As[c4*4+2][r] = v.z;
            As[c4*4+3][r] = v.w;
        }
        #pragma unroll
        for (int i = 0; i < B_LOADS; i++) {
            int idx = tid + i*THREADS;
            int r  = idx / (BN/4);
            int c4 = idx % (BN/4);
            *(float4*)&Bs[r][c4*4] =
                *(const float4*)&Bm[(size_t)(k0 + r)*ldb + colBase + c4*4];
        }
        __syncthreads();

        #pragma unroll
        for (int k = 0; k < BK; k++) {
            float ra[TM], rb[TN];
            #pragma unroll
            for (int i = 0; i < TM; i++) ra[i] = As[k][ty*TM + i];
            #pragma unroll
            for (int j = 0; j < TN; j++) rb[j] = Bs[k][tx*TN + j];
            #pragma unroll
            for (int i = 0; i < TM; i++)
                #pragma unroll
                for (int j = 0; j < TN; j++)
                    acc[i][j] += ra[i]*rb[j];
        }
        __syncthreads();
    }

    #pragma unroll
    for (int i = 0; i < TM; i++) {
        int r = rowBase + ty*TM + i;
        #pragma unroll
        for (int j = 0; j < TN; j++) {
            int c = colBase + tx*TN + j;
            float v = acc[i][j];
            if (ACT == 1) {
                v += bias[c];
                v = (v > 20.f) ? v : log1pf(expf(v));
            }
            C[(size_t)r*ldc + c] = v;
        }
    }
}

// ---------------- depthwise causal conv1d (K=4) + bias + SiLU --------------
__global__ void conv_silu_kernel(const float* __restrict__ xz,
                                 const float* __restrict__ w,
                                 const float* __restrict__ bias,
                                 float* __restrict__ out)
{
    int idx = blockIdx.x*blockDim.x + threadIdx.x;
    if (idx >= BB*LL*ED) return;
    int e = idx % ED;
    int l = (idx / ED) % LL;
    int b = idx / (ED*LL);

    const float4 wv = *(const float4*)&w[e*4];
    const float* base = xz + (size_t)b*LL*2*ED + e;

    float s = bias[e];
    if (l >= 3) s += wv.x * base[(size_t)(l-3)*2*ED];
    if (l >= 2) s += wv.y * base[(size_t)(l-2)*2*ED];
    if (l >= 1) s += wv.z * base[(size_t)(l-1)*2*ED];
    s += wv.w * base[(size_t)l*2*ED];

    out[idx] = s / (1.f + __expf(-s));
}

// ---------------- fused selective scan v2: thread-per-e, 16 states in regs -
__global__ __launch_bounds__(32)
void scan2_kernel(const float* __restrict__ delta,  // (B,L,ED)
                  const float* __restrict__ dbc,    // (BL,96)
                  const float* __restrict__ xconv,  // (B,L,ED)
                  const float* __restrict__ xz,     // (B,L,2ED), z at +ED
                  const float* __restrict__ A_log,  // (ED,16)
                  const float* __restrict__ Dw,     // (ED,)
                  __nv_bfloat16* __restrict__ yh,
                  __nv_bfloat16* __restrict__ yl)
{
    const int b   = blockIdx.y;
    const int tid = threadIdx.x;
    const int e   = blockIdx.x * 32 + tid;

    __shared__ __align__(16) float sBC[128][36];   // [li][0..15]=B, [16..31]=C

    float an[16];
    bool ok = true;
    #pragma unroll
    for (int n = 0; n < 16; n++) {
        an[n] = -__expf(A_log[e*NSTATE + n]);
        ok = ok && (fabsf(an[n] + (float)(n+1)) < 1e-4f * (float)(n+1));
    }
    const float Dval = Dw[e];

    const float* dRow   = delta + (size_t)b*LL*ED + e;
    const float* xRow   = xconv + (size_t)b*LL*ED + e;
    const float* zRow   = xz    + (size_t)b*LL*2*ED + ED + e;
    const float* bcBase = dbc   + (size_t)b*LL*96;
    __nv_bfloat16* yhRow = yh + (size_t)b*LL*ED + e;
    __nv_bfloat16* ylRow = yl + (size_t)b*LL*ED + e;

    float h[16];
    #pragma unroll
    for (int n = 0; n < 16; n++) h[n] = 0.f;

    float pd[2][4], px[2][4], pz[2][4];
    #pragma unroll
    for (int j = 0; j < 4; j++) {
        pd[0][j] = dRow[(size_t)j*ED];
        px[0][j] = xRow[(size_t)j*ED];
        pz[0][j] = zRow[(size_t)j*2*ED];
    }

    for (int g = 0; g < LL/4; g++) {
        const int l0 = g * 4;
        if ((l0 & 127) == 0) {
            __syncwarp();
            for (int i = tid; i < 128*8; i += 32) {
                const int li = i >> 3, q = i & 7;
                const float4 v = *(const float4*)&bcBase[(size_t)(l0+li)*96 + DTRANK + q*4];
                *(float4*)&sBC[li][q*4] = v;
            }
            __syncwarp();
        }
        const int cur = g & 1, nxt = cur ^ 1;
        if (g + 1 < LL/4) {
            const int l1 = l0 + 4;
            #pragma unroll
            for (int j = 0; j < 4; j++) {
                pd[nxt][j] = dRow[(size_t)(l1+j)*ED];
                px[nxt][j] = xRow[(size_t)(l1+j)*ED];
                pz[nxt][j] = zRow[(size_t)(l1+j)*2*ED];
            }
        }
        #pragma unroll
        for (int j = 0; j < 4; j++) {
            const int li = (l0 & 127) + j;
            const float dv = pd[cur][j], xv = px[cur][j], zv = pz[cur][j];
            const float bx = dv * xv;

            float Bv[16], Cv[16];
            #pragma unroll
            for (int q = 0; q < 4; q++) {
                const float4 vb = *(const float4*)&sBC[li][q*4];
                Bv[q*4+0]=vb.x; Bv[q*4+1]=vb.y; Bv[q*4+2]=vb.z; Bv[q*4+3]=vb.w;
                const float4 vc = *(const float4*)&sBC[li][16 + q*4];
                Cv[q*4+0]=vc.x; Cv[q*4+1]=vc.y; Cv[q*4+2]=vc.z; Cv[q*4+3]=vc.w;
            }

            float dA[16];
            if (ok) {
                const float t1  = __expf(-dv);
                const float t2  = t1*t1;
                const float t3  = t2*t1;
                const float t4  = t2*t2;
                const float t8  = t4*t4;
                const float t12 = t8*t4;
                dA[0]=t1;      dA[1]=t2;      dA[2]=t3;      dA[3]=t4;
                dA[4]=t4*t1;   dA[5]=t4*t2;   dA[6]=t4*t3;   dA[7]=t8;
                dA[8]=t8*t1;   dA[9]=t8*t2;   dA[10]=t8*t3;  dA[11]=t12;
                dA[12]=t12*t1; dA[13]=t12*t2; dA[14]=t12*t3; dA[15]=t8*t8;
            } else {
                #pragma unroll
                for (int n = 0; n < 16; n++) dA[n] = __expf(dv * an[n]);
            }

            float y0=0.f, y1=0.f, y2=0.f, y3=0.f;
            #pragma unroll
            for (int n = 0; n < 4; n++) { h[n] = dA[n]*h[n] + bx*Bv[n]; y0 += h[n]*Cv[n]; }
            #pragma unroll
            for (int n = 4; n < 8; n++) { h[n] = dA[n]*h[n] + bx*Bv[n]; y1 += h[n]*Cv[n]; }
            #pragma unroll
            for (int n = 8; n < 12; n++){ h[n] = dA[n]*h[n] + bx*Bv[n]; y2 += h[n]*Cv[n]; }
            #pragma unroll
            for (int n = 12; n < 16; n++){h[n] = dA[n]*h[n] + bx*Bv[n]; y3 += h[n]*Cv[n]; }

            float yv = (y0 + y1) + (y2 + y3) + Dval * xv;
            const float sil = zv / (1.f + __expf(-zv));
            yv *= sil;

            const int l = l0 + j;
            const __nv_bfloat16 hh = __float2bfloat16(yv);
            yhRow[(size_t)l*ED] = hh;
            ylRow[(size_t)l*ED] = __float2bfloat16(yv - __bfloat162float(hh));
        }
    }
}

// ---------------- launch ---------------------------------------------------
extern "C" void kernel_launch(void* const* d_in, const int* in_sizes, int n_in,
                              void* d_out, int out_size)
{
    const float* x          = (const float*)d_in[0];  // (B,L,1024)
    const float* in_proj_w  = (const float*)d_in[1];  // (1024,4096)
    const float* conv_w     = (const float*)d_in[2];  // (2048,1,4)
    const float* conv_b     = (const float*)d_in[3];  // (2048,)
    const float* x_proj_w   = (const float*)d_in[4];  // (2048,96)
    const float* dt_proj_w  = (const float*)d_in[5];  // (64,2048)
    const float* dt_proj_b  = (const float*)d_in[6];  // (2048,)
    const float* A_log      = (const float*)d_in[7];  // (2048,16)
    const float* Dw         = (const float*)d_in[8];  // (2048,)
    const float* out_proj_w = (const float*)d_in[9];  // (2048,1024)
    float* out = (float*)d_out;                       // (B,L,1024)

    float *xzP, *xconvP, *dbcP, *deltaP;
    cudaGetSymbolAddress((void**)&xzP,    g_xz);
    cudaGetSymbolAddress((void**)&xconvP, g_xconv);
    cudaGetSymbolAddress((void**)&dbcP,   g_dbc);
    cudaGetSymbolAddress((void**)&deltaP, g_delta);

    __nv_bfloat16 *xhP, *xlP, *w1hP, *w1lP, *yhP, *ylP, *w6hP, *w6lP;
    cudaGetSymbolAddress((void**)&xhP,  g_xh);
    cudaGetSymbolAddress((void**)&xlP,  g_xl);
    cudaGetSymbolAddress((void**)&w1hP, g_w1h);
    cudaGetSymbolAddress((void**)&w1lP, g_w1l);
    cudaGetSymbolAddress((void**)&yhP,  g_yh);
    cudaGetSymbolAddress((void**)&ylP,  g_yl);
    cudaGetSymbolAddress((void**)&w6hP, g_w6h);
    cudaGetSymbolAddress((void**)&w6lP, g_w6l);

    cudaFuncSetAttribute(gemm_bf16x3,
                         cudaFuncAttributeMaxDynamicSharedMemorySize, GSM_BYTES);

    // 0) weight transpose + split
    wconv_kernel<<<dim3(2*ED/32, DMODEL/32), dim3(32,8)>>>(in_proj_w,  w1hP, w1lP, DMODEL, 2*ED);
    wconv_kernel<<<dim3(DMODEL/32, ED/32),   dim3(32,8)>>>(out_proj_w, w6hP, w6lP, ED, DMODEL);

    // 0b) x split
    aconv_kernel<<<(BL*DMODEL + 255)/256, 256>>>(x, xhP, xlP, BL*DMODEL);

    // 1) xz = x @ W1 : (2048 x 4096), K=1024 — bf16x3 mma.sync
    gemm_bf16x3<<<dim3(2*ED/128, BL/128), 256, GSM_BYTES>>>(
        xhP, xlP, w1hP, w1lP, xzP, BL, 2*ED, DMODEL);

    // 2) depthwise causal conv + SiLU -> xconv
    conv_silu_kernel<<<(BB*LL*ED + 255)/256, 256>>>(xzP, conv_w, conv_b, xconvP);

    // 3) dbc = xconv @ x_proj_w : (2048 x 96), K=2048
    {
        dim3 grid(2, BL/32);
        sgemm_kernel<32,48,32,2,6,0><<<grid, 128>>>(
            xconvP, x_proj_w, dbcP, BL, 96, ED, ED, 96, 96, nullptr);
    }

    // 4) delta = softplus(dbc[:, :64] @ dt_proj_w + b) : (2048 x 2048), K=64
    {
        dim3 grid(ED/64, BL/64);
        sgemm_kernel<64,64,16,4,4,1><<<grid, 256>>>(
            dbcP, dt_proj_w, deltaP, BL, ED, DTRANK, 96, ED, ED, dt_proj_b);
    }

    // 5) fused selective scan v2 -> yh/yl bf16 split directly
    {
        dim3 grid(ED/32, BB);
        scan2_kernel<<<grid, 32>>>(deltaP, dbcP, xconvP, xzP, A_log, Dw, yhP, ylP);
    }

    // 6) out = y @ W6 : (2048 x 1024), K=2048 — bf16x3 mma.sync
    gemm_bf16x3<<<dim3(DMODEL/128, BL/128), 256, GSM_BYTES>>>(
        yhP, ylP, w6hP, w6lP, out, BL, DMODEL, ED);
}

// round 9
// speedup vs baseline: 2.3672x; 1.0493x over previous
#include <cuda_runtime.h>
#include <cuda_bf16.h>
#include <cstdint>

// ---------------- problem constants ----------------------------------------
#define BB 2
#define LL 1024
#define DMODEL 1024
#define ED 2048
#define NSTATE 16
#define DTRANK 64
#define BL (BB*LL)          // 2048 rows
#define KSPL 8              // dbc split-K factor

// ---------------- scratch (no allocation allowed -> __device__ globals) ----
__device__ __align__(128) float g_xz[BB*LL*2*ED];      // (B,L,4096)
__device__ __align__(128) float g_xconv[BB*LL*ED];     // (B,L,2048)
__device__ __align__(128) float g_dbc[BL*96];          // (BL,96)
__device__ __align__(128) float g_dbc_part[KSPL*BL*96];// split-K partials
__device__ __align__(128) float g_delta[BB*LL*ED];     // (B,L,2048)

// bf16 split-precision scratch
__device__ __align__(128) __nv_bfloat16 g_xh[BL*DMODEL];
__device__ __align__(128) __nv_bfloat16 g_xl[BL*DMODEL];
__device__ __align__(128) __nv_bfloat16 g_w1h[2*ED*DMODEL];
__device__ __align__(128) __nv_bfloat16 g_w1l[2*ED*DMODEL];
__device__ __align__(128) __nv_bfloat16 g_yh[BL*ED];
__device__ __align__(128) __nv_bfloat16 g_yl[BL*ED];
__device__ __align__(128) __nv_bfloat16 g_w6h[DMODEL*ED];
__device__ __align__(128) __nv_bfloat16 g_w6l[DMODEL*ED];

// ---------------- PTX helpers (sm_80-level only: no tcgen05/TMA!) ----------
__device__ __forceinline__ uint32_t smem_u32(const void* p) {
    uint32_t a;
    asm("{ .reg .u64 t; cvta.to.shared.u64 t, %1; cvt.u32.u64 %0, t; }"
        : "=r"(a) : "l"(p));
    return a;
}

#define CP_ASYNC16(dst, src) \
    asm volatile("cp.async.cg.shared.global [%0], [%1], 16;" \
                 :: "r"(dst), "l"(src) : "memory")
#define CP_COMMIT() asm volatile("cp.async.commit_group;" ::: "memory")
#define CP_WAIT(n)  asm volatile("cp.async.wait_group %0;" :: "n"(n) : "memory")

#define LDSM_X4(r0,r1,r2,r3, addr) \
    asm volatile("ldmatrix.sync.aligned.m8n8.x4.shared.b16 {%0,%1,%2,%3}, [%4];" \
                 : "=r"(r0),"=r"(r1),"=r"(r2),"=r"(r3) : "r"(addr))

__device__ __forceinline__ void mma_bf16(float* c, const uint32_t* a, const uint32_t* b) {
    asm volatile(
        "mma.sync.aligned.m16n8k16.row.col.f32.bf16.bf16.f32 "
        "{%0,%1,%2,%3}, {%4,%5,%6,%7}, {%8,%9}, {%0,%1,%2,%3};"
        : "+f"(c[0]), "+f"(c[1]), "+f"(c[2]), "+f"(c[3])
        : "r"(a[0]), "r"(a[1]), "r"(a[2]), "r"(a[3]), "r"(b[0]), "r"(b[1]));
}

// ---------------- bf16x3 mma.sync GEMM: C(M,N) = A(M,K) * Bt(N,K)^T --------
// CTA 128x128, BK=32, 8 warps of 64x32. 2-stage pipeline, 2 CTAs/SM.
#define TPAD 40                          // bf16 elems per smem row (80 B)
#define TILE_B (128*TPAD*2)              // 10240 B per tile
#define STAGE_B (4*TILE_B)               // Ah,Al,Bh,Bl
#define GSM_BYTES (2*STAGE_B)            // 81920 B

__global__ __launch_bounds__(256, 2)
void gemm_bf16x3(const __nv_bfloat16* __restrict__ Ah, const __nv_bfloat16* __restrict__ Al,
                 const __nv_bfloat16* __restrict__ Bh, const __nv_bfloat16* __restrict__ Bl,
                 float* __restrict__ C, int M, int N, int K)
{
    extern __shared__ __align__(128) char smem[];
    const uint32_t sb = smem_u32(smem);
    const int tid  = threadIdx.x;
    const int lane = tid & 31;
    const int warp = tid >> 5;
    const int wm   = warp >> 2;          // 0..1  (M)
    const int wn   = warp & 3;           // 0..3  (N)
    const int m0 = blockIdx.y * 128, n0 = blockIdx.x * 128;
    const int NK = K >> 5;               // K/32 chunks

    const __nv_bfloat16* gbase[4] = {
        Ah + (size_t)m0 * K, Al + (size_t)m0 * K,
        Bh + (size_t)n0 * K, Bl + (size_t)n0 * K };

    auto loadStage = [&](int kc) {
        const uint32_t stg = sb + (uint32_t)(kc & 1) * STAGE_B;
        const int koff = kc * 32;
        #pragma unroll
        for (int i = 0; i < 8; i++) {
            const int c  = tid + i * 256;
            const int t  = c >> 9;
            const int cc = c & 511;
            const int row = cc >> 2, q = cc & 3;
            const __nv_bfloat16* src = gbase[t] + (size_t)row * K + koff + q * 8;
            const uint32_t dst = stg + t * TILE_B + (row * TPAD + q * 8) * 2;
            CP_ASYNC16(dst, src);
        }
    };

    float acc[4][4][4];
    #pragma unroll
    for (int i = 0; i < 4; i++)
        #pragma unroll
        for (int j = 0; j < 4; j++)
            #pragma unroll
            for (int k = 0; k < 4; k++) acc[i][j][k] = 0.f;

    const uint32_t aRow = (uint32_t)(wm * 64 + (lane & 15)) * (TPAD * 2)
                        + (uint32_t)(lane >> 4) * 16;
    const uint32_t bRow = (uint32_t)(wn * 32 + ((lane >> 4) & 1) * 8 + (lane & 7)) * (TPAD * 2)
                        + (uint32_t)((lane >> 3) & 1) * 16;

    loadStage(0);
    CP_COMMIT();

    for (int kc = 0; kc < NK; kc++) {
        if (kc + 1 < NK) { loadStage(kc + 1); CP_COMMIT(); CP_WAIT(1); }
        else             { CP_WAIT(0); }
        __syncthreads();

        const uint32_t stg = sb + (uint32_t)(kc & 1) * STAGE_B;
        const uint32_t sAh = stg,            sAl = stg + TILE_B;
        const uint32_t sBh = stg + 2*TILE_B, sBl = stg + 3*TILE_B;

        #pragma unroll
        for (int ks = 0; ks < 2; ks++) {
            const uint32_t kOff = ks * 32;

            uint32_t bh[4][2], bl[4][2];
            #pragma unroll
            for (int p = 0; p < 2; p++) {
                const uint32_t ro = bRow + (uint32_t)p * 16 * (TPAD * 2) + kOff;
                LDSM_X4(bh[2*p][0], bh[2*p][1], bh[2*p+1][0], bh[2*p+1][1], sBh + ro);
                LDSM_X4(bl[2*p][0], bl[2*p][1], bl[2*p+1][0], bl[2*p+1][1], sBl + ro);
            }
            #pragma unroll
            for (int mf = 0; mf < 4; mf++) {
                const uint32_t ro = aRow + (uint32_t)mf * 16 * (TPAD * 2) + kOff;
                uint32_t ah[4], al[4];
                LDSM_X4(ah[0], ah[1], ah[2], ah[3], sAh + ro);
                LDSM_X4(al[0], al[1], al[2], al[3], sAl + ro);
                #pragma unroll
                for (int nf = 0; nf < 4; nf++) {
                    mma_bf16(acc[mf][nf], ah, bh[nf]);
                    mma_bf16(acc[mf][nf], ah, bl[nf]);
                    mma_bf16(acc[mf][nf], al, bh[nf]);
                }
            }
        }
        __syncthreads();
    }

    const int mBase = m0 + wm * 64 + (lane >> 2);
    const int nBase = n0 + wn * 32 + (lane & 3) * 2;
    #pragma unroll
    for (int mf = 0; mf < 4; mf++)
        #pragma unroll
        for (int nf = 0; nf < 4; nf++) {
            const int r = mBase + mf * 16;
            const int c = nBase + nf * 8;
            *(float2*)&C[(size_t)r * N + c]       = make_float2(acc[mf][nf][0], acc[mf][nf][1]);
            *(float2*)&C[(size_t)(r + 8) * N + c] = make_float2(acc[mf][nf][2], acc[mf][nf][3]);
        }
}

// ---------------- weight transpose + bf16 hi/lo split ----------------------
__global__ void wconv_kernel(const float* __restrict__ W,
                             __nv_bfloat16* __restrict__ Th,
                             __nv_bfloat16* __restrict__ Tl, int K, int N)
{
    __shared__ float t[32][33];
    const int bx = blockIdx.x * 32;  // n
    const int by = blockIdx.y * 32;  // k
    const int tx = threadIdx.x, ty = threadIdx.y;
    #pragma unroll
    for (int j = 0; j < 32; j += 8)
        t[ty + j][tx] = W[(size_t)(by + ty + j) * N + bx + tx];
    __syncthreads();
    #pragma unroll
    for (int j = 0; j < 32; j += 8) {
        const float v = t[tx][ty + j];
        const __nv_bfloat16 h = __float2bfloat16(v);
        const float r = v - __bfloat162float(h);
        const size_t o = (size_t)(bx + ty + j) * K + by + tx;
        Th[o] = h;  Tl[o] = __float2bfloat16(r);
    }
}

// ---------------- activation bf16 hi/lo split ------------------------------
__global__ void aconv_kernel(const float* __restrict__ A,
                             __nv_bfloat16* __restrict__ H,
                             __nv_bfloat16* __restrict__ L, int n)
{
    const int i = blockIdx.x * blockDim.x + threadIdx.x;
    if (i >= n) return;
    const float v = A[i];
    const __nv_bfloat16 h = __float2bfloat16(v);
    H[i] = h;
    L[i] = __float2bfloat16(v - __bfloat162float(h));
}

// ---------------- fp32 SIMT SGEMM (delta GEMM) -----------------------------
template<int BM,int BN,int BK,int TM,int TN,int ACT>
__global__ void sgemm_kernel(const float* __restrict__ A,
                             const float* __restrict__ Bm,
                             float* __restrict__ C,
                             int M, int N, int K,
                             int lda, int ldb, int ldc,
                             const float* __restrict__ bias)
{
    constexpr int THREADS = (BM/TM)*(BN/TN);
    __shared__ float As[BK][BM];
    __shared__ float Bs[BK][BN];

    const int tid = threadIdx.x;
    const int tx  = tid % (BN/TN);
    const int ty  = tid / (BN/TN);
    const int rowBase = blockIdx.y * BM;
    const int colBase = blockIdx.x * BN;

    float acc[TM][TN];
    #pragma unroll
    for (int i = 0; i < TM; i++)
        #pragma unroll
        for (int j = 0; j < TN; j++) acc[i][j] = 0.f;

    constexpr int A_LOADS = (BM*BK/4) / THREADS;
    constexpr int B_LOADS = (BK*BN/4) / THREADS;
    static_assert(A_LOADS*THREADS == BM*BK/4, "A tile not divisible");
    static_assert(B_LOADS*THREADS == BK*BN/4, "B tile not divisible");

    for (int k0 = 0; k0 < K; k0 += BK) {
        #pragma unroll
        for (int i = 0; i < A_LOADS; i++) {
            int idx = tid + i*THREADS;
            int r  = idx / (BK/4);
            int c4 = idx % (BK/4);
            float4 v = *(const float4*)&A[(size_t)(rowBase + r)*lda + k0 + c4*4];
            As[c4*4+0][r] = v.x;
            As[c4*4+1][r] = v.y;
            As[c4*4+2][r] = v.z;
            As[c4*4+3][r] = v.w;
        }
        #pragma unroll
        for (int i = 0; i < B_LOADS; i++) {
            int idx = tid + i*THREADS;
            int r  = idx / (BN/4);
            int c4 = idx % (BN/4);
            *(float4*)&Bs[r][c4*4] =
                *(const float4*)&Bm[(size_t)(k0 + r)*ldb + colBase + c4*4];
        }
        __syncthreads();

        #pragma unroll
        for (int k = 0; k < BK; k++) {
            float ra[TM], rb[TN];
            #pragma unroll
            for (int i = 0; i < TM; i++) ra[i] = As[k][ty*TM + i];
            #pragma unroll
            for (int j = 0; j < TN; j++) rb[j] = Bs[k][tx*TN + j];
            #pragma unroll
            for (int i = 0; i < TM; i++)
                #pragma unroll
                for (int j = 0; j < TN; j++)
                    acc[i][j] += ra[i]*rb[j];
        }
        __syncthreads();
    }

    #pragma unroll
    for (int i = 0; i < TM; i++) {
        int r = rowBase + ty*TM + i;
        #pragma unroll
        for (int j = 0; j < TN; j++) {
            int c = colBase + tx*TN + j;
            float v = acc[i][j];
            if (ACT == 1) {
                v += bias[c];
                v = (v > 20.f) ? v : log1pf(expf(v));
            }
            C[(size_t)r*ldc + c] = v;
        }
    }
}

// ---------------- dbc split-K SGEMM: 64x96 tile, K slice per blockIdx.z ----
// part[z] = xconv[:, z*256:(z+1)*256] @ x_proj_w[z*256:(z+1)*256, :]
__global__ __launch_bounds__(256)
void dbc_split_kernel(const float* __restrict__ A,   // (BL, ED)
                      const float* __restrict__ Bm,  // (ED, 96)
                      float* __restrict__ part)      // (KSPL, BL, 96)
{
    constexpr int BM = 64, BN = 96, BK = 32, TM = 4, TN = 6;
    constexpr int THREADS = (BM/TM)*(BN/TN);      // 256
    constexpr int KSUB = ED / KSPL;               // 256
    __shared__ float As[BK][BM];
    __shared__ float Bs[BK][BN];

    const int tid = threadIdx.x;
    const int tx  = tid % (BN/TN);                // 0..15
    const int ty  = tid / (BN/TN);                // 0..15
    const int rowBase = blockIdx.y * BM;
    const int kBase   = blockIdx.z * KSUB;
    float* C = part + (size_t)blockIdx.z * BL * 96;

    float acc[TM][TN];
    #pragma unroll
    for (int i = 0; i < TM; i++)
        #pragma unroll
        for (int j = 0; j < TN; j++) acc[i][j] = 0.f;

    for (int k0 = 0; k0 < KSUB; k0 += BK) {
        // A tile: 64x32 = 512 float4 / 256 threads = 2 each
        #pragma unroll
        for (int i = 0; i < 2; i++) {
            int idx = tid + i*THREADS;
            int r  = idx / (BK/4);
            int c4 = idx % (BK/4);
            float4 v = *(const float4*)&A[(size_t)(rowBase + r)*ED + kBase + k0 + c4*4];
            As[c4*4+0][r] = v.x;
            As[c4*4+1][r] = v.y;
            As[c4*4+2][r] = v.z;
            As[c4*4+3][r] = v.w;
        }
        // B tile: 32x96 = 768 float4 / 256 threads = 3 each
        #pragma unroll
        for (int i = 0; i < 3; i++) {
            int idx = tid + i*THREADS;
            int r  = idx / (BN/4);
            int c4 = idx % (BN/4);
            *(float4*)&Bs[r][c4*4] =
                *(const float4*)&Bm[(size_t)(kBase + k0 + r)*96 + c4*4];
        }
        __syncthreads();

        #pragma unroll
        for (int k = 0; k < BK; k++) {
            float ra[TM], rb[TN];
            #pragma unroll
            for (int i = 0; i < TM; i++) ra[i] = As[k][ty*TM + i];
            #pragma unroll
            for (int j = 0; j < TN; j++) rb[j] = Bs[k][tx*TN + j];
            #pragma unroll
            for (int i = 0; i < TM; i++)
                #pragma unroll
                for (int j = 0; j < TN; j++)
                    acc[i][j] += ra[i]*rb[j];
        }
        __syncthreads();
    }

    #pragma unroll
    for (int i = 0; i < TM; i++) {
        int r = rowBase + ty*TM + i;
        #pragma unroll
        for (int j = 0; j < TN; j++)
            C[(size_t)r*96 + tx*TN + j] = acc[i][j];
    }
}

__global__ void dbc_reduce_kernel(const float* __restrict__ part,
                                  float* __restrict__ out)
{
    const int i = blockIdx.x * blockDim.x + threadIdx.x;
    if (i >= BL*96) return;
    float s = 0.f;
    #pragma unroll
    for (int p = 0; p < KSPL; p++) s += part[(size_t)p*BL*96 + i];
    out[i] = s;
}

// ---------------- depthwise causal conv1d (K=4) + bias + SiLU --------------
__global__ void conv_silu_kernel(const float* __restrict__ xz,
                                 const float* __restrict__ w,
                                 const float* __restrict__ bias,
                                 float* __restrict__ out)
{
    int idx = blockIdx.x*blockDim.x + threadIdx.x;
    if (idx >= BB*LL*ED) return;
    int e = idx % ED;
    int l = (idx / ED) % LL;
    int b = idx / (ED*LL);

    const float4 wv = *(const float4*)&w[e*4];
    const float* base = xz + (size_t)b*LL*2*ED + e;

    float s = bias[e];
    if (l >= 3) s += wv.x * base[(size_t)(l-3)*2*ED];
    if (l >= 2) s += wv.y * base[(size_t)(l-2)*2*ED];
    if (l >= 1) s += wv.z * base[(size_t)(l-1)*2*ED];
    s += wv.w * base[(size_t)l*2*ED];

    out[idx] = s / (1.f + __expf(-s));
}

// ---------------- fused selective scan v3: 4 threads/e, 4 states each ------
// grid (ED/32, BB), block 128. Thread (ep, g): e = blk*32+ep, states g*4..g*4+3.
__global__ __launch_bounds__(128)
void scan3_kernel(const float* __restrict__ delta,  // (B,L,ED)
                  const float* __restrict__ dbc,    // (BL,96)
                  const float* __restrict__ xconv,  // (B,L,ED)
                  const float* __restrict__ xz,     // (B,L,2ED), z at +ED
                  const float* __restrict__ A_log,  // (ED,16)
                  const float* __restrict__ Dw,     // (ED,)
                  __nv_bfloat16* __restrict__ yh,
                  __nv_bfloat16* __restrict__ yl)
{
    const int b   = blockIdx.y;
    const int tid = threadIdx.x;
    const int g   = tid & 3;          // state group
    const int ep  = tid >> 2;         // 0..31
    const int e   = blockIdx.x * 32 + ep;

    __shared__ __align__(16) float sBC[128][36];   // [li][0..15]=B, [16..31]=C

    float an[4];
    bool ok = true;
    #pragma unroll
    for (int j = 0; j < 4; j++) {
        const int n = g*4 + j;
        an[j] = -__expf(A_log[e*NSTATE + n]);
        ok = ok && (fabsf(an[j] + (float)(n+1)) < 1e-4f * (float)(n+1));
    }
    const float Dval = Dw[e];

    const float* dRow   = delta + (size_t)b*LL*ED + e;
    const float* xRow   = xconv + (size_t)b*LL*ED + e;
    const float* zRow   = xz    + (size_t)b*LL*2*ED + ED + e;
    const float* bcBase = dbc   + (size_t)b*LL*96;
    __nv_bfloat16* yhRow = yh + (size_t)b*LL*ED + e;
    __nv_bfloat16* ylRow = yl + (size_t)b*LL*ED + e;

    float h[4] = {0.f, 0.f, 0.f, 0.f};

    float pd[2][4], px[2][4], pz[2][4];
    #pragma unroll
    for (int j = 0; j < 4; j++) {
        pd[0][j] = dRow[(size_t)j*ED];
        px[0][j] = xRow[(size_t)j*ED];
        pz[0][j] = zRow[(size_t)j*2*ED];
    }

    for (int gi = 0; gi < LL/4; gi++) {
        const int l0 = gi * 4;
        if ((l0 & 127) == 0) {
            __syncthreads();                       // prior window fully consumed
            for (int i = tid; i < 128*8; i += 128) {
                const int li = i >> 3, q = i & 7;
                const float4 v = *(const float4*)&bcBase[(size_t)(l0+li)*96 + DTRANK + q*4];
                *(float4*)&sBC[li][q*4] = v;
            }
            __syncthreads();
        }
        const int cur = gi & 1, nxt = cur ^ 1;
        if (gi + 1 < LL/4) {
            const int l1 = l0 + 4;
            #pragma unroll
            for (int j = 0; j < 4; j++) {
                pd[nxt][j] = dRow[(size_t)(l1+j)*ED];
                px[nxt][j] = xRow[(size_t)(l1+j)*ED];
                pz[nxt][j] = zRow[(size_t)(l1+j)*2*ED];
            }
        }
        #pragma unroll
        for (int j = 0; j < 4; j++) {
            const int li = (l0 & 127) + j;
            const float dv = pd[cur][j], xv = px[cur][j], zv = pz[cur][j];
            const float bx = dv * xv;

            const float4 vb = *(const float4*)&sBC[li][g*4];        // B[g*4..g*4+3]
            const float4 vc = *(const float4*)&sBC[li][16 + g*4];   // C[g*4..g*4+3]

            float dA[4];
            if (ok) {
                const float t1 = __expf(-dv);
                const float t2 = t1*t1;
                const float t3 = t2*t1;
                const float t4 = t2*t2;
                float tg = 1.f;                 // t^(4g)
                if (g & 1) tg *= t4;
                if (g & 2) tg *= t4*t4;
                dA[0] = tg*t1; dA[1] = tg*t2; dA[2] = tg*t3; dA[3] = tg*t4;
            } else {
                #pragma unroll
                for (int n = 0; n < 4; n++) dA[n] = __expf(dv * an[n]);
            }

            float yp = 0.f;
            h[0] = dA[0]*h[0] + bx*vb.x;  yp += h[0]*vc.x;
            h[1] = dA[1]*h[1] + bx*vb.y;  yp += h[1]*vc.y;
            h[2] = dA[2]*h[2] + bx*vb.z;  yp += h[2]*vc.z;
            h[3] = dA[3]*h[3] + bx*vb.w;  yp += h[3]*vc.w;

            yp += __shfl_xor_sync(0xffffffffu, yp, 1);
            yp += __shfl_xor_sync(0xffffffffu, yp, 2);

            if (g == 0) {
                float yv = yp + Dval * xv;
                const float sil = zv / (1.f + __expf(-zv));
                yv *= sil;
                const int l = l0 + j;
                const __nv_bfloat16 hh = __float2bfloat16(yv);
                yhRow[(size_t)l*ED] = hh;
                ylRow[(size_t)l*ED] = __float2bfloat16(yv - __bfloat162float(hh));
            }
        }
    }
}

// ---------------- launch ---------------------------------------------------
extern "C" void kernel_launch(void* const* d_in, const int* in_sizes, int n_in,
                              void* d_out, int out_size)
{
    const float* x          = (const float*)d_in[0];  // (B,L,1024)
    const float* in_proj_w  = (const float*)d_in[1];  // (1024,4096)
    const float* conv_w     = (const float*)d_in[2];  // (2048,1,4)
    const float* conv_b     = (const float*)d_in[3];  // (2048,)
    const float* x_proj_w   = (const float*)d_in[4];  // (2048,96)
    const float* dt_proj_w  = (const float*)d_in[5];  // (64,2048)
    const float* dt_proj_b  = (const float*)d_in[6];  // (2048,)
    const float* A_log      = (const float*)d_in[7];  // (2048,16)
    const float* Dw         = (const float*)d_in[8];  // (2048,)
    const float* out_proj_w = (const float*)d_in[9];  // (2048,1024)
    float* out = (float*)d_out;                       // (B,L,1024)

    float *xzP, *xconvP, *dbcP, *dbcPartP, *deltaP;
    cudaGetSymbolAddress((void**)&xzP,      g_xz);
    cudaGetSymbolAddress((void**)&xconvP,   g_xconv);
    cudaGetSymbolAddress((void**)&dbcP,     g_dbc);
    cudaGetSymbolAddress((void**)&dbcPartP, g_dbc_part);
    cudaGetSymbolAddress((void**)&deltaP,   g_delta);

    __nv_bfloat16 *xhP, *xlP, *w1hP, *w1lP, *yhP, *ylP, *w6hP, *w6lP;
    cudaGetSymbolAddress((void**)&xhP,  g_xh);
    cudaGetSymbolAddress((void**)&xlP,  g_xl);
    cudaGetSymbolAddress((void**)&w1hP, g_w1h);
    cudaGetSymbolAddress((void**)&w1lP, g_w1l);
    cudaGetSymbolAddress((void**)&yhP,  g_yh);
    cudaGetSymbolAddress((void**)&ylP,  g_yl);
    cudaGetSymbolAddress((void**)&w6hP, g_w6h);
    cudaGetSymbolAddress((void**)&w6lP, g_w6l);

    cudaFuncSetAttribute(gemm_bf16x3,
                         cudaFuncAttributeMaxDynamicSharedMemorySize, GSM_BYTES);

    // 0) weight transpose + split
    wconv_kernel<<<dim3(2*ED/32, DMODEL/32), dim3(32,8)>>>(in_proj_w,  w1hP, w1lP, DMODEL, 2*ED);
    wconv_kernel<<<dim3(DMODEL/32, ED/32),   dim3(32,8)>>>(out_proj_w, w6hP, w6lP, ED, DMODEL);

    // 0b) x split
    aconv_kernel<<<(BL*DMODEL + 255)/256, 256>>>(x, xhP, xlP, BL*DMODEL);

    // 1) xz = x @ W1 : (2048 x 4096), K=1024 — bf16x3 mma.sync
    gemm_bf16x3<<<dim3(2*ED/128, BL/128), 256, GSM_BYTES>>>(
        xhP, xlP, w1hP, w1lP, xzP, BL, 2*ED, DMODEL);

    // 2) depthwise causal conv + SiLU -> xconv
    conv_silu_kernel<<<(BB*LL*ED + 255)/256, 256>>>(xzP, conv_w, conv_b, xconvP);

    // 3) dbc = xconv @ x_proj_w : split-K=8, deterministic partials + reduce
    {
        dim3 grid(1, BL/64, KSPL);     // 256 blocks
        dbc_split_kernel<<<grid, 256>>>(xconvP, x_proj_w, dbcPartP);
        dbc_reduce_kernel<<<(BL*96 + 255)/256, 256>>>(dbcPartP, dbcP);
    }

    // 4) delta = softplus(dbc[:, :64] @ dt_proj_w + b) : (2048 x 2048), K=64
    {
        dim3 grid(ED/64, BL/64);
        sgemm_kernel<64,64,16,4,4,1><<<grid, 256>>>(
            dbcP, dt_proj_w, deltaP, BL, ED, DTRANK, 96, ED, ED, dt_proj_b);
    }

    // 5) fused selective scan v3 -> yh/yl bf16 split directly
    {
        dim3 grid(ED/32, BB);
        scan3_kernel<<<grid, 128>>>(deltaP, dbcP, xconvP, xzP, A_log, Dw, yhP, ylP);
    }

    // 6) out = y @ W6 : (2048 x 1024), K=2048 — bf16x3 mma.sync
    gemm_bf16x3<<<dim3(DMODEL/128, BL/128), 256, GSM_BYTES>>>(
        yhP, ylP, w6hP, w6lP, out, BL, DMODEL, ED);
}